// round 14
// baseline (speedup 1.0000x reference)
#include <cuda_runtime.h>
#include <cuda_fp16.h>
#include <math.h>

#define B_   64
#define N_   197
#define C_   768
#define H_   12
#define R_   98
#define K_   99
#define NKEPT_ 98
#define THRK_ 1941
#define ALPHA_ 0.1f
#define EPS_ 1e-5f
#define BH_  (B_*H_)
#define NP_  224

// ---------------- scratch ----------------
__device__ __half   g_attnh[(size_t)BH_*256*NP_];
__device__ float    g_diag[(size_t)BH_*N_];
__device__ float    g_x1  [(size_t)B_*N_*C_];
__device__ float    g_x2  [(size_t)B_*K_*C_];
__device__ int      g_ik  [B_*K_];
__device__ int      g_ie  [B_*R_];
__device__ unsigned g_hh  [(size_t)B_*N_*C_/2];
__device__ unsigned g_hl  [(size_t)B_*N_*C_/2];
__device__ __half   g_wqkvh[(size_t)C_*3*C_];
__device__ __half   g_wqkvl[(size_t)C_*3*C_];
__device__ __half   g_wprojh[(size_t)C_*C_];
__device__ __half   g_wfc1h[(size_t)C_*4*C_];
__device__ __half   g_wfc2h[(size_t)4*C_*C_];
__device__ __half   g_qh[(size_t)BH_*NP_*64];
__device__ __half   g_ql[(size_t)BH_*NP_*64];
__device__ __half   g_kh[(size_t)BH_*NP_*64];
__device__ __half   g_kl[(size_t)BH_*NP_*64];
__device__ __half   g_vh[(size_t)B_*NP_*C_];
__device__ unsigned g_aoh [(size_t)B_*N_*C_/2];
__device__ unsigned g_h2h [(size_t)B_*K_*C_/2];
__device__ unsigned g_mlph[(size_t)B_*K_*4*C_/2];

// ---------------- helpers ----------------
__device__ __forceinline__ unsigned packh2(float a, float b) {
    __half2 h = __floats2half2_rn(a, b);
    return *reinterpret_cast<unsigned*>(&h);
}
__device__ __forceinline__ void splith2(float a, float b, unsigned& hi, unsigned& lo) {
    __half ah = __float2half_rn(a), bh = __float2half_rn(b);
    __half2 h = __halves2half2(ah, bh);
    hi = *reinterpret_cast<unsigned*>(&h);
    lo = packh2(a - __half2float(ah), b - __half2float(bh));
}
__device__ __forceinline__ unsigned sm_u32(const void* p) {
    return (unsigned)__cvta_generic_to_shared(p);
}
__device__ __forceinline__ void ldsm4(unsigned r[4], unsigned a) {
    asm volatile("ldmatrix.sync.aligned.m8n8.x4.shared.b16 {%0,%1,%2,%3}, [%4];"
                 : "=r"(r[0]), "=r"(r[1]), "=r"(r[2]), "=r"(r[3]) : "r"(a));
}
__device__ __forceinline__ void ldsm4t(unsigned r[4], unsigned a) {
    asm volatile("ldmatrix.sync.aligned.m8n8.x4.trans.shared.b16 {%0,%1,%2,%3}, [%4];"
                 : "=r"(r[0]), "=r"(r[1]), "=r"(r[2]), "=r"(r[3]) : "r"(a));
}
__device__ __forceinline__ void mma_f16(float c[4], const unsigned a[4], const unsigned b[2]) {
    asm volatile(
        "mma.sync.aligned.m16n8k16.row.col.f32.f16.f16.f32 "
        "{%0,%1,%2,%3},{%4,%5,%6,%7},{%8,%9},{%0,%1,%2,%3};"
        : "+f"(c[0]), "+f"(c[1]), "+f"(c[2]), "+f"(c[3])
        : "r"(a[0]), "r"(a[1]), "r"(a[2]), "r"(a[3]), "r"(b[0]), "r"(b[1]));
}

// ---------------- fused weight convert ----------------
#define S0_ (768*2304/8)
#define S1_ (S0_ + 768*768/8)
#define S2_ (S1_ + 768*3072/8)
#define S3_ (S2_ + 3072*768/8)
__global__ void cvtw_all(const float* __restrict__ wqkv, const float* __restrict__ wproj,
                         const float* __restrict__ wfc1, const float* __restrict__ wfc2,
                         __half* __restrict__ qkvh, __half* __restrict__ qkvl,
                         __half* __restrict__ projh, __half* __restrict__ fc1h,
                         __half* __restrict__ fc2h)
{
    int i8 = blockIdx.x * 256 + threadIdx.x;
    if (i8 >= S3_) return;
    const float* src; __half* dsth; __half* dstl = nullptr; int base;
    if (i8 < S0_)      { src = wqkv;  dsth = qkvh;  dstl = qkvl; base = 0; }
    else if (i8 < S1_) { src = wproj; dsth = projh; base = S0_; }
    else if (i8 < S2_) { src = wfc1;  dsth = fc1h;  base = S1_; }
    else               { src = wfc2;  dsth = fc2h;  base = S2_; }
    int i = (i8 - base) * 8;
    float4 a = *(const float4*)&src[i];
    float4 b = *(const float4*)&src[i + 4];
    __half2 h[4];
    h[0] = __floats2half2_rn(a.x, a.y); h[1] = __floats2half2_rn(a.z, a.w);
    h[2] = __floats2half2_rn(b.x, b.y); h[3] = __floats2half2_rn(b.z, b.w);
    *(uint4*)&dsth[i] = *(uint4*)h;
    if (dstl) {
        __half2 l[4];
        l[0] = __floats2half2_rn(a.x - __low2float(h[0]), a.y - __high2float(h[0]));
        l[1] = __floats2half2_rn(a.z - __low2float(h[1]), a.w - __high2float(h[1]));
        l[2] = __floats2half2_rn(b.x - __low2float(h[2]), b.y - __high2float(h[2]));
        l[3] = __floats2half2_rn(b.z - __low2float(h[3]), b.w - __high2float(h[3]));
        *(uint4*)&dstl[i] = *(uint4*)l;
    }
}

// ---------------- LayerNorm -> packed fp16 hi(/lo) ----------------
template<int SPLIT>
__global__ void ln_pack_kernel(const float* __restrict__ x, const float* __restrict__ g,
                               const float* __restrict__ bta,
                               unsigned* __restrict__ hi, unsigned* __restrict__ lo)
{
    int row = blockIdx.x;
    const float2* xr = (const float2*)(x + (size_t)row * C_);
    int tid = threadIdx.x;
    float2 v1 = xr[tid];
    float2 v2 = make_float2(0.f, 0.f);
    if (tid < 128) v2 = xr[tid + 256];
    float s = v1.x + v1.y + v2.x + v2.y;
    float ss = v1.x * v1.x + v1.y * v1.y + v2.x * v2.x + v2.y * v2.y;
    for (int off = 16; off; off >>= 1) {
        s  += __shfl_xor_sync(0xffffffffu, s, off);
        ss += __shfl_xor_sync(0xffffffffu, ss, off);
    }
    __shared__ float rs[8], rss[8];
    __shared__ float smean, srstd;
    int w = tid >> 5;
    if ((tid & 31) == 0) { rs[w] = s; rss[w] = ss; }
    __syncthreads();
    if (tid == 0) {
        float S = 0.f, SS = 0.f;
        for (int i = 0; i < 8; i++) { S += rs[i]; SS += rss[i]; }
        float mean = S * (1.f / C_);
        float var = SS * (1.f / C_) - mean * mean;
        smean = mean; srstd = rsqrtf(var + EPS_);
    }
    __syncthreads();
    float mean = smean, rstd = srstd;
    size_t base = (size_t)row * (C_ / 2);
#pragma unroll
    for (int p = 0; p < 2; p++) {
        if (p == 1 && tid >= 128) break;
        int wi = tid + p * 256;
        float2 v = (p == 0) ? v1 : v2;
        int c = wi * 2;
        float a = (v.x - mean) * rstd * g[c] + bta[c];
        float b = (v.y - mean) * rstd * g[c + 1] + bta[c + 1];
        if (SPLIT) { unsigned h, l; splith2(a, b, h, l); hi[base + wi] = h; lo[base + wi] = l; }
        else hi[base + wi] = packh2(a, b);
    }
}

// ---------------- fp16 GEMM: 64xNT tile, grid-stride tiles ----------------
// EPI: 0 = bias+res -> float; 1 = bias+gelu -> packed half; 2 = QK split head-major; 3 = V head-major
#define AST 40
#define ABUF (64 * AST)

template<int SPLIT, int NT>
__device__ __forceinline__ void hg_compute(const __half* buf, const int aoff[2],
                                           const int* boff, float (*acc)[4])
{
    const int BSTc = NT + 8;
    const int BBUFc = 32 * BSTc;
    const int NF = NT / 32;
    const __half* AsH = buf;
    const __half* AsL = buf + ABUF;
    const __half* BsH = buf + ABUF * (1 + SPLIT);
    const __half* BsL = BsH + BBUFc;
#pragma unroll
    for (int s = 0; s < 2; s++) {
        unsigned ah[2][4], al[2][4];
#pragma unroll
        for (int mf = 0; mf < 2; mf++) {
            ldsm4(ah[mf], sm_u32(AsH + aoff[mf] + s * 16));
            if (SPLIT) ldsm4(al[mf], sm_u32(AsL + aoff[mf] + s * 16));
        }
        unsigned bhf[NF][2], blf[NF][2];
#pragma unroll
        for (int p = 0; p < NF / 2; p++) {
            unsigned r[4];
            ldsm4t(r, sm_u32(BsH + boff[p] + s * 16 * BSTc));
            bhf[2*p][0] = r[0]; bhf[2*p][1] = r[1];
            bhf[2*p+1][0] = r[2]; bhf[2*p+1][1] = r[3];
            if (SPLIT) {
                unsigned rl[4];
                ldsm4t(rl, sm_u32(BsL + boff[p] + s * 16 * BSTc));
                blf[2*p][0] = rl[0]; blf[2*p][1] = rl[1];
                blf[2*p+1][0] = rl[2]; blf[2*p+1][1] = rl[3];
            }
        }
#pragma unroll
        for (int mf = 0; mf < 2; mf++)
#pragma unroll
            for (int nf = 0; nf < NF; nf++) {
                mma_f16(acc[mf * NF + nf], ah[mf], bhf[nf]);
                if (SPLIT) {
                    mma_f16(acc[mf * NF + nf], ah[mf], blf[nf]);
                    mma_f16(acc[mf * NF + nf], al[mf], bhf[nf]);
                }
            }
    }
}

template<int SPLIT, int EPI, int NT>
__global__ void __launch_bounds__(256, 2)
hgemm_kernel(const unsigned* __restrict__ Ah, const unsigned* __restrict__ Al,
             const __half* __restrict__ Bh, const __half* __restrict__ Bl,
             const float* __restrict__ bias, const float* __restrict__ res,
             float* __restrict__ Cf, unsigned* __restrict__ Cu,
             unsigned* __restrict__ qh, unsigned* __restrict__ ql,
             unsigned* __restrict__ kh, unsigned* __restrict__ kl,
             unsigned* __restrict__ vh,
             int Nd, int Kd, int ldc, int n0ofs, int ntx, int ntiles)
{
    extern __shared__ __half sh[];
    const int BSTc = NT + 8;
    const int BBUFc = 32 * BSTc;
    const int NF = NT / 32;
    const int RP = 2048 / NT;
    const int NPASS = NT / 64;
    const int UNIT = (ABUF + BBUFc) * (1 + SPLIT);
    int tid = threadIdx.x, lane = tid & 31, wid = tid >> 5;
    int wm = wid & 1, wn = wid >> 1;
    int g = lane >> 2, tg = lane & 3;
    int Kw = Kd / 2;

    int aoff[2], boff[NF / 2];
#pragma unroll
    for (int mf = 0; mf < 2; mf++)
        aoff[mf] = (wm * 32 + mf * 16 + (lane & 15)) * AST + (lane >> 4) * 8;
#pragma unroll
    for (int p = 0; p < NF / 2; p++)
        boff[p] = (lane & 15) * BSTc + wn * (NT / 4) + p * 16 + (lane >> 4) * 8;

    for (int t = blockIdx.x; t < ntiles; t += gridDim.x) {
        int bx = t % ntx, by = t / ntx;
        int m0 = by * 64, n0 = bx * NT + n0ofs;
        __syncthreads();   // protect shared buffers from previous tile

        float acc[2 * NF][4];
#pragma unroll
        for (int i = 0; i < 2 * NF; i++)
#pragma unroll
            for (int q = 0; q < 4; q++) acc[i][q] = 0.f;

        int ar = tid >> 2;
        int bkr = tid / (NT / 8), bn8 = (tid % (NT / 8)) * 8;
        const unsigned* ApH = Ah + (size_t)(m0 + ar) * Kw + (tid & 3) * 4;
        const unsigned* ApL = SPLIT ? Al + (size_t)(m0 + ar) * Kw + (tid & 3) * 4 : ApH;
        const __half* BpH = Bh + (size_t)bkr * Nd + n0 + bn8;
        const __half* BpL = SPLIT ? Bl + (size_t)bkr * Nd + n0 + bn8 : BpH;

        int aSts = ar * AST + (tid & 3) * 8;
        int bSts = bkr * BSTc + bn8;

        uint4 rah, ral, rbh[NPASS], rbl[NPASS];
        rah = *(const uint4*)ApH;
        if (SPLIT) ral = *(const uint4*)ApL;
#pragma unroll
        for (int j = 0; j < NPASS; j++) {
            rbh[j] = *(const uint4*)(BpH + (size_t)(j * RP) * Nd);
            if (SPLIT) rbl[j] = *(const uint4*)(BpL + (size_t)(j * RP) * Nd);
        }
        {
            __half* buf = sh;
            *(uint4*)&buf[aSts] = rah;
            if (SPLIT) *(uint4*)&buf[ABUF + aSts] = ral;
            __half* bb = buf + ABUF * (1 + SPLIT);
#pragma unroll
            for (int j = 0; j < NPASS; j++) {
                *(uint4*)&bb[bSts + j * RP * BSTc] = rbh[j];
                if (SPLIT) *(uint4*)&bb[BBUFc + bSts + j * RP * BSTc] = rbl[j];
            }
        }
        __syncthreads();

        int nit = Kd / 32;
        for (int it = 1; it < nit; it++) {
            rah = *(const uint4*)(ApH + it * 16);
            if (SPLIT) ral = *(const uint4*)(ApL + it * 16);
#pragma unroll
            for (int j = 0; j < NPASS; j++) {
                rbh[j] = *(const uint4*)(BpH + (size_t)(it * 32 + j * RP) * Nd);
                if (SPLIT) rbl[j] = *(const uint4*)(BpL + (size_t)(it * 32 + j * RP) * Nd);
            }
            hg_compute<SPLIT, NT>(sh + ((it - 1) & 1) * UNIT, aoff, boff, acc);
            {
                __half* buf = sh + (it & 1) * UNIT;
                *(uint4*)&buf[aSts] = rah;
                if (SPLIT) *(uint4*)&buf[ABUF + aSts] = ral;
                __half* bb = buf + ABUF * (1 + SPLIT);
#pragma unroll
                for (int j = 0; j < NPASS; j++) {
                    *(uint4*)&bb[bSts + j * RP * BSTc] = rbh[j];
                    if (SPLIT) *(uint4*)&bb[BBUFc + bSts + j * RP * BSTc] = rbl[j];
                }
            }
            __syncthreads();
        }
        hg_compute<SPLIT, NT>(sh + ((nit - 1) & 1) * UNIT, aoff, boff, acc);

        // epilogue
#pragma unroll
        for (int mf = 0; mf < 2; mf++) {
            int row = m0 + wm * 32 + mf * 16 + g;
#pragma unroll
            for (int nf = 0; nf < NF; nf++) {
                int col = n0 + wn * (NT / 4) + nf * 8 + 2 * tg;
                float b0 = 0.f, b1 = 0.f;
                if (EPI == 0 || EPI == 1) { b0 = bias[col]; b1 = bias[col + 1]; }
#pragma unroll
                for (int half = 0; half < 2; half++) {
                    int r = row + half * 8;
                    float c0 = acc[mf * NF + nf][half * 2 + 0] + b0;
                    float c1 = acc[mf * NF + nf][half * 2 + 1] + b1;
                    if (EPI == 0) {
                        size_t base = (size_t)r * ldc + col;
                        float2 rv = *(const float2*)&res[base];
                        float2 ov; ov.x = c0 + rv.x; ov.y = c1 + rv.y;
                        *(float2*)&Cf[base] = ov;
                    } else if (EPI == 1) {
                        c0 = 0.5f * c0 * (1.f + erff(c0 * 0.70710678118654752f));
                        c1 = 0.5f * c1 * (1.f + erff(c1 * 0.70710678118654752f));
                        Cu[(size_t)r * (Nd / 2) + col / 2] = packh2(c0, c1);
                    } else if (EPI == 2) {
                        int b = r / N_, m = r - b * N_;
                        int part = col >= 768;
                        int rem = col - (part ? 768 : 0);
                        int hd = rem >> 6, d = rem & 63;
                        float s0 = c0, s1 = c1;
                        if (!part) { s0 *= 0.125f; s1 *= 0.125f; }
                        unsigned h, l;
                        splith2(s0, s1, h, l);
                        size_t o = ((size_t)(b * H_ + hd) * NP_ + m) * 32 + (d >> 1);
                        (part ? kh : qh)[o] = h;
                        (part ? kl : ql)[o] = l;
                    } else {
                        int b = r / N_, m = r - b * N_;
                        int cv = col - 1536;
                        vh[((size_t)b * NP_ + m) * 384 + (cv >> 1)] = packh2(c0, c1);
                    }
                }
            }
        }
    }
}

// ---------------- fused scores + softmax + AV ----------------
#define PSTR 232   // halves per prob row in shared
__global__ void fsmav_kernel(const __half* __restrict__ qhg, const __half* __restrict__ qlg,
                             const __half* __restrict__ khg, const __half* __restrict__ klg,
                             const __half* __restrict__ vhg,
                             float* __restrict__ diagg, __half* __restrict__ attnh,
                             unsigned* __restrict__ aoh)
{
    extern __shared__ unsigned dsm[];
    unsigned* Qh = dsm;                        // 64*36
    unsigned* Ql = Qh + 64 * 36;
    unsigned* Kh = Ql + 64 * 36;               // 32*73
    unsigned* Kl = Kh + 32 * 73;
    unsigned* Ps = Kl + 32 * 73;               // 64*(PSTR/2)
    float* red = (float*)(Ps + 64 * (PSTR / 2));

    int bh = blockIdx.x, b = bh / H_, hh = bh % H_;
    int m0 = blockIdx.y * 64;
    int tid = threadIdx.x, lane = tid & 31, wid = tid >> 5;
    int g = lane >> 2, tg = lane & 3;
    int wm = wid & 3, wn = wid >> 2;
    const unsigned* qhw = (const unsigned*)qhg;
    const unsigned* qlw = (const unsigned*)qlg;
    const unsigned* khw = (const unsigned*)khg;
    const unsigned* klw = (const unsigned*)klg;

#pragma unroll
    for (int r = 0; r < 2; r++) {
        int idx = tid + r * 256;
        int row = idx >> 3, w4 = (idx & 7) * 4;
        size_t src = ((size_t)bh * NP_ + m0 + row) * 32 + w4;
        *(uint4*)&Qh[row * 36 + w4] = *(const uint4*)&qhw[src];
        *(uint4*)&Ql[row * 36 + w4] = *(const uint4*)&qlw[src];
    }

    float acc[4][4][4];
#pragma unroll
    for (int c = 0; c < 4; c++)
#pragma unroll
        for (int j = 0; j < 4; j++)
#pragma unroll
            for (int q = 0; q < 4; q++) acc[c][j][q] = 0.f;

    for (int c = 0; c < 4; c++) {
        int n0 = c * 64;
        __syncthreads();
#pragma unroll
        for (int r = 0; r < 2; r++) {
            int idx = tid + r * 256;
            int token = idx >> 3, wp = idx & 7;
            uint4 vh4 = make_uint4(0u, 0u, 0u, 0u), vl4 = make_uint4(0u, 0u, 0u, 0u);
            if (n0 + token < NP_) {
                size_t src = ((size_t)bh * NP_ + n0 + token) * 32 + wp * 4;
                vh4 = *(const uint4*)&khw[src];
                vl4 = *(const uint4*)&klw[src];
            }
            Kh[(wp * 4 + 0) * 73 + token] = vh4.x;
            Kh[(wp * 4 + 1) * 73 + token] = vh4.y;
            Kh[(wp * 4 + 2) * 73 + token] = vh4.z;
            Kh[(wp * 4 + 3) * 73 + token] = vh4.w;
            Kl[(wp * 4 + 0) * 73 + token] = vl4.x;
            Kl[(wp * 4 + 1) * 73 + token] = vl4.y;
            Kl[(wp * 4 + 2) * 73 + token] = vl4.z;
            Kl[(wp * 4 + 3) * 73 + token] = vl4.w;
        }
        __syncthreads();
#pragma unroll
        for (int s = 0; s < 4; s++) {
            int abase = (wm * 16 + g) * 36 + s * 8 + tg;
            unsigned ah[4] = {Qh[abase], Qh[abase + 8 * 36], Qh[abase + 4], Qh[abase + 8 * 36 + 4]};
            unsigned al[4] = {Ql[abase], Ql[abase + 8 * 36], Ql[abase + 4], Ql[abase + 8 * 36 + 4]};
#pragma unroll
            for (int nf = 0; nf < 4; nf++) {
                int n = wn * 32 + nf * 8 + g;
                unsigned bhf[2] = {Kh[(s * 8 + tg) * 73 + n], Kh[(s * 8 + tg + 4) * 73 + n]};
                unsigned blf[2] = {Kl[(s * 8 + tg) * 73 + n], Kl[(s * 8 + tg + 4) * 73 + n]};
                mma_f16(acc[c][nf], ah, bhf);
                mma_f16(acc[c][nf], ah, blf);
                mma_f16(acc[c][nf], al, bhf);
            }
        }
    }

#pragma unroll
    for (int nf = 0; nf < 4; nf++) {
        int col = 192 + wn * 32 + nf * 8 + 2 * tg;
        if (col >= N_)     { acc[3][nf][0] = -1e30f; acc[3][nf][2] = -1e30f; }
        if (col + 1 >= N_) { acc[3][nf][1] = -1e30f; acc[3][nf][3] = -1e30f; }
    }

    int lr0 = wm * 16 + g, lr1 = lr0 + 8;
    float mx0 = -1e30f, mx1 = -1e30f;
#pragma unroll
    for (int c = 0; c < 4; c++)
#pragma unroll
        for (int nf = 0; nf < 4; nf++) {
            mx0 = fmaxf(mx0, fmaxf(acc[c][nf][0], acc[c][nf][1]));
            mx1 = fmaxf(mx1, fmaxf(acc[c][nf][2], acc[c][nf][3]));
        }
    mx0 = fmaxf(mx0, __shfl_xor_sync(0xffffffffu, mx0, 1));
    mx0 = fmaxf(mx0, __shfl_xor_sync(0xffffffffu, mx0, 2));
    mx1 = fmaxf(mx1, __shfl_xor_sync(0xffffffffu, mx1, 1));
    mx1 = fmaxf(mx1, __shfl_xor_sync(0xffffffffu, mx1, 2));
    if (tg == 0) { red[(0 * 2 + wn) * 64 + lr0] = mx0; red[(0 * 2 + wn) * 64 + lr1] = mx1; }
    __syncthreads();
    mx0 = fmaxf(red[0 * 64 + lr0], red[1 * 64 + lr0]);
    mx1 = fmaxf(red[0 * 64 + lr1], red[1 * 64 + lr1]);

    float s0 = 0.f, s1 = 0.f;
#pragma unroll
    for (int c = 0; c < 4; c++)
#pragma unroll
        for (int nf = 0; nf < 4; nf++) {
            float e0 = expf(acc[c][nf][0] - mx0);
            float e1 = expf(acc[c][nf][1] - mx0);
            float e2 = expf(acc[c][nf][2] - mx1);
            float e3 = expf(acc[c][nf][3] - mx1);
            acc[c][nf][0] = e0; acc[c][nf][1] = e1;
            acc[c][nf][2] = e2; acc[c][nf][3] = e3;
            s0 += e0 + e1; s1 += e2 + e3;
        }
    s0 += __shfl_xor_sync(0xffffffffu, s0, 1);
    s0 += __shfl_xor_sync(0xffffffffu, s0, 2);
    s1 += __shfl_xor_sync(0xffffffffu, s1, 1);
    s1 += __shfl_xor_sync(0xffffffffu, s1, 2);
    __syncthreads();                    // red reuse
    if (tg == 0) { red[(0 * 2 + wn) * 64 + lr0] = s0; red[(0 * 2 + wn) * 64 + lr1] = s1; }
    __syncthreads();
    float inv0 = 1.f / (red[0 * 64 + lr0] + red[1 * 64 + lr0]);
    float inv1 = 1.f / (red[0 * 64 + lr1] + red[1 * 64 + lr1]);

    int row0 = m0 + lr0, row1 = m0 + lr1;
    unsigned* hout = (unsigned*)attnh;
#pragma unroll
    for (int c = 0; c < 4; c++)
#pragma unroll
        for (int nf = 0; nf < 4; nf++) {
            int col = c * 64 + wn * 32 + nf * 8 + 2 * tg;
            float v00 = acc[c][nf][0] * inv0, v01 = acc[c][nf][1] * inv0;
            float v10 = acc[c][nf][2] * inv1, v11 = acc[c][nf][3] * inv1;
            if (row0 < N_) {
                if (col == row0)          diagg[(size_t)bh * N_ + row0] = v00;
                else if (col + 1 == row0) diagg[(size_t)bh * N_ + row0] = v01;
            }
            if (row1 < N_) {
                if (col == row1)          diagg[(size_t)bh * N_ + row1] = v10;
                else if (col + 1 == row1) diagg[(size_t)bh * N_ + row1] = v11;
            }
            if (col < NP_) {
                unsigned p0 = packh2(v00, v01), p1 = packh2(v10, v11);
                hout[((size_t)bh * 256 + row0) * 112 + col / 2] = p0;
                hout[((size_t)bh * 256 + row1) * 112 + col / 2] = p1;
                Ps[lr0 * (PSTR / 2) + col / 2] = p0;
                Ps[lr1 * (PSTR / 2) + col / 2] = p1;
            }
        }
    __syncthreads();

    // ---- AV from shared probs ----
    const __half* Psh = (const __half*)Ps;
    __half* Vs = (__half*)Kh;          // 32x72 halves
    float acc2[4][4];
#pragma unroll
    for (int i = 0; i < 4; i++)
#pragma unroll
        for (int j = 0; j < 4; j++) acc2[i][j] = 0.f;

    int aoff2 = (wm * 16 + (lane & 15)) * PSTR + (lane >> 4) * 8;
    int boff2[2];
#pragma unroll
    for (int p = 0; p < 2; p++)
        boff2[p] = (lane & 15) * 72 + wn * 32 + p * 16 + (lane >> 4) * 8;

    for (int k0 = 0; k0 < NP_; k0 += 32) {
        __syncthreads();
        {
            int token = tid >> 3, n8 = (tid & 7) * 8;
            const __half* src = vhg + ((size_t)b * NP_ + k0 + token) * C_ + hh * 64 + n8;
            *(uint4*)&Vs[token * 72 + n8] = *(const uint4*)src;
        }
        __syncthreads();
#pragma unroll
        for (int s = 0; s < 2; s++) {
            unsigned ah[4];
            ldsm4(ah, sm_u32(Psh + aoff2 + k0 + s * 16));
#pragma unroll
            for (int p = 0; p < 2; p++) {
                unsigned r[4];
                ldsm4t(r, sm_u32(Vs + boff2[p] + s * 16 * 72));
                unsigned b0[2] = {r[0], r[1]}, b1[2] = {r[2], r[3]};
                mma_f16(acc2[2*p],   ah, b0);
                mma_f16(acc2[2*p+1], ah, b1);
            }
        }
    }
#pragma unroll
    for (int nf = 0; nf < 4; nf++) {
        int col = wn * 32 + nf * 8 + 2 * tg;
#pragma unroll
        for (int hf = 0; hf < 2; hf++) {
            int m = m0 + wm * 16 + g + hf * 8;
            if (m < N_)
                aoh[(size_t)(b * N_ + m) * 384 + (hh * 64 + col) / 2] =
                    packh2(acc2[nf][hf * 2 + 0], acc2[nf][hf * 2 + 1]);
        }
    }
}

// ---------------- selection ----------------
__global__ void select_kernel(const float* __restrict__ diagg, int* __restrict__ ik,
                              int* __restrict__ ie)
{
    __shared__ float diag[196];
    __shared__ int kept[196];
    int b = blockIdx.x, tid = threadIdx.x;
    if (tid < 196) {
        float s = 0.f;
        for (int hh = 0; hh < H_; hh++)
            s += diagg[(size_t)(b * H_ + hh) * N_ + tid + 1];
        diag[tid] = s;
    }
    __syncthreads();
    if (tid < 196) {
        float di = diag[tid];
        int rank = 0;
        for (int j = 0; j < 196; j++) {
            float dj = diag[j];
            rank += (dj > di) || (dj == di && j < tid);
        }
        kept[tid] = (rank < NKEPT_) ? 1 : 0;
    }
    __syncthreads();
    if (tid < 196) {
        int mine = kept[tid];
        int pos = 0;
        for (int j = 0; j < tid; j++) pos += (kept[j] == mine);
        if (mine) ik[b * K_ + 1 + pos] = tid + 1;
        else      ie[b * R_ + pos]     = tid + 1;
    }
    if (tid == 0) ik[b * K_] = 0;
}

// ---------------- propagation ----------------
#define PT_ 38
__global__ void propagate_kernel(const __half* __restrict__ attnh, const float* __restrict__ x1,
                                 const int* __restrict__ ikg, const int* __restrict__ ieg,
                                 float* __restrict__ x2)
{
    extern __shared__ float sm[];
    float* ws = sm;
    float* xe = sm + K_ * R_;
    __shared__ int ik[K_], ie[R_];
    __shared__ int cnt;
    int bh = blockIdx.x;
    int b = bh / H_, hh = bh % H_;
    int tid = threadIdx.x;
    if (tid < K_) ik[tid] = ikg[b * K_ + tid];
    if (tid < R_) ie[tid] = ieg[b * R_ + tid];
    __syncthreads();
    const __half* ablk = attnh + (size_t)bh * 256 * NP_;
    unsigned uv[PT_];
#pragma unroll
    for (int j = 0; j < PT_; j++) {
        int idx = tid + j * 256;
        float w = 0.f;
        if (idx < K_ * R_) {
            int k = idx / R_, e = idx - k * R_;
            w = __half2float(ablk[(size_t)ik[k] * NP_ + ie[e]]);
            ws[idx] = w;
        }
        uv[j] = __float_as_uint(w);
    }
    for (int idx = tid; idx < R_ * 64; idx += 256) {
        int e = idx >> 6, d = idx & 63;
        xe[idx] = x1[(size_t)(b * N_ + ie[e]) * 768 + hh * 64 + d];
    }
    __syncthreads();

    unsigned lo = 0u, hi = 0x3f801000u;
    while (lo < hi) {
        unsigned mid = lo + ((hi - lo + 1) >> 1);
        if (tid == 0) cnt = 0;
        __syncthreads();
        int local = 0;
#pragma unroll
        for (int j = 0; j < PT_; j++) local += (uv[j] >= mid);
        for (int off = 16; off; off >>= 1) local += __shfl_xor_sync(0xffffffffu, local, off);
        if ((tid & 31) == 0) atomicAdd(&cnt, local);
        __syncthreads();
        int c = cnt;
        __syncthreads();
        if (c >= THRK_) lo = mid; else hi = mid - 1;
    }
    float thr = __uint_as_float(lo);

    for (int p = tid; p < K_ * 64; p += 256) {
        int k = p >> 6, d = p & 63;
        const float* wr = ws + k * R_;
        float acc = 0.f;
#pragma unroll 2
        for (int e = 0; e < R_; e++) {
            float wv = wr[e];
            wv = (wv >= thr) ? wv : 0.f;
            acc = fmaf(wv, xe[e * 64 + d], acc);
        }
        x2[(size_t)(b * K_ + k) * 768 + hh * 64 + d] =
            x1[(size_t)(b * N_ + ik[k]) * 768 + hh * 64 + d] + ALPHA_ * acc;
    }
}

// ---------------- host ----------------
extern "C" void kernel_launch(void* const* d_in, const int* in_sizes, int n_in,
                              void* d_out, int out_size)
{
    const float* x     = (const float*)d_in[0];
    const float* n1g   = (const float*)d_in[1];
    const float* n1b   = (const float*)d_in[2];
    const float* qkvw  = (const float*)d_in[3];
    const float* projw = (const float*)d_in[4];
    const float* projb = (const float*)d_in[5];
    const float* n2g   = (const float*)d_in[6];
    const float* n2b   = (const float*)d_in[7];
    const float* fc1w  = (const float*)d_in[8];
    const float* fc1b  = (const float*)d_in[9];
    const float* fc2w  = (const float*)d_in[10];
    const float* fc2b  = (const float*)d_in[11];
    float* out = (float*)d_out;

    float *diagg, *x1, *x2;
    int *ik, *ie;
    unsigned *hh, *hl, *aoh, *h2h, *mlph;
    __half *wqkvh, *wqkvl, *wprojh, *wfc1h, *wfc2h, *attnh, *qh, *ql, *kh, *kl, *vh;
    cudaGetSymbolAddress((void**)&diagg, g_diag);
    cudaGetSymbolAddress((void**)&attnh, g_attnh);
    cudaGetSymbolAddress((void**)&x1,   g_x1);
    cudaGetSymbolAddress((void**)&x2,   g_x2);
    cudaGetSymbolAddress((void**)&ik,   g_ik);
    cudaGetSymbolAddress((void**)&ie,   g_ie);
    cudaGetSymbolAddress((void**)&hh,   g_hh);
    cudaGetSymbolAddress((void**)&hl,   g_hl);
    cudaGetSymbolAddress((void**)&wqkvh, g_wqkvh);
    cudaGetSymbolAddress((void**)&wqkvl, g_wqkvl);
    cudaGetSymbolAddress((void**)&wprojh, g_wprojh);
    cudaGetSymbolAddress((void**)&wfc1h, g_wfc1h);
    cudaGetSymbolAddress((void**)&wfc2h, g_wfc2h);
    cudaGetSymbolAddress((void**)&qh,   g_qh);
    cudaGetSymbolAddress((void**)&ql,   g_ql);
    cudaGetSymbolAddress((void**)&kh,   g_kh);
    cudaGetSymbolAddress((void**)&kl,   g_kl);
    cudaGetSymbolAddress((void**)&vh,   g_vh);
    cudaGetSymbolAddress((void**)&aoh,  g_aoh);
    cudaGetSymbolAddress((void**)&h2h,  g_h2h);
    cudaGetSymbolAddress((void**)&mlph, g_mlph);

    const int PROP_SMEM = (K_ * R_ + R_ * 64) * 4;
    cudaFuncSetAttribute(propagate_kernel, cudaFuncAttributeMaxDynamicSharedMemorySize, PROP_SMEM);
    const int SMEM_P256 = (ABUF + 32 * 264) * 2 * 2;
    const int SMEM_S256 = (ABUF + 32 * 264) * 4 * 2;
    const int SMEM_P128 = (ABUF + 32 * 136) * 2 * 2;
    const int SMEM_FSMAV = (64*36*2 + 32*73*2 + 64*(PSTR/2)) * 4 + 256 * 4;
    cudaFuncSetAttribute(hgemm_kernel<1, 2, 256>, cudaFuncAttributeMaxDynamicSharedMemorySize, SMEM_S256);
    cudaFuncSetAttribute(hgemm_kernel<0, 3, 256>, cudaFuncAttributeMaxDynamicSharedMemorySize, SMEM_P256);
    cudaFuncSetAttribute(hgemm_kernel<0, 0, 256>, cudaFuncAttributeMaxDynamicSharedMemorySize, SMEM_P256);
    cudaFuncSetAttribute(hgemm_kernel<0, 1, 256>, cudaFuncAttributeMaxDynamicSharedMemorySize, SMEM_P256);
    cudaFuncSetAttribute(hgemm_kernel<0, 0, 128>, cudaFuncAttributeMaxDynamicSharedMemorySize, SMEM_P128);
    cudaFuncSetAttribute(fsmav_kernel, cudaFuncAttributeMaxDynamicSharedMemorySize, SMEM_FSMAV);

    // 0. weight conversion
    cvtw_all<<<(S3_ + 255) / 256, 256>>>(qkvw, projw, fc1w, fc2w,
                                         wqkvh, wqkvl, wprojh, wfc1h, wfc2h);
    // 1. LN1
    ln_pack_kernel<1><<<B_ * N_, 256>>>(x, n1g, n1b, hh, hl);
    // 2a. QK (split) -> head-major split-fp16 q/k  (1182 tiles)
    hgemm_kernel<1, 2, 256><<<1182, 256, SMEM_S256>>>(
        hh, hl, wqkvh, wqkvl, nullptr, nullptr, nullptr, nullptr,
        (unsigned*)qh, (unsigned*)ql, (unsigned*)kh, (unsigned*)kl, nullptr,
        2304, C_, 0, 0, 6, 1182);
    // 2b. V -> head-major fp16 (591 tiles)
    hgemm_kernel<0, 3, 256><<<591, 256, SMEM_P256>>>(
        hh, nullptr, wqkvh, nullptr, nullptr, nullptr, nullptr, nullptr,
        nullptr, nullptr, nullptr, nullptr, (unsigned*)vh,
        2304, C_, 0, 1536, 3, 591);
    // 3. fused scores + softmax + AV
    fsmav_kernel<<<dim3(BH_, 4), 256, SMEM_FSMAV>>>(qh, ql, kh, kl, vh, diagg, attnh, aoh);
    // 4. proj + bias + residual (591 tiles)
    hgemm_kernel<0, 0, 256><<<591, 256, SMEM_P256>>>(
        aoh, nullptr, wprojh, nullptr, projb, x, x1, nullptr,
        nullptr, nullptr, nullptr, nullptr, nullptr,
        C_, C_, C_, 0, 3, 591);
    // 5. selection
    select_kernel<<<B_, 256>>>(diagg, ik, ie);
    // 6. propagation
    propagate_kernel<<<BH_, 256, PROP_SMEM>>>(attnh, x1, ik, ie, x2);
    // 7. LN2
    ln_pack_kernel<0><<<B_ * K_, 256>>>(x2, n2g, n2b, h2h, nullptr);
    // 8. fc1 + gelu (1188 tiles on 1184 persistent blocks: no straggler wave)
    hgemm_kernel<0, 1, 256><<<1184, 256, SMEM_P256>>>(
        h2h, nullptr, wfc1h, nullptr, fc1b, nullptr, nullptr, mlph,
        nullptr, nullptr, nullptr, nullptr, nullptr,
        4 * C_, C_, 0, 0, 12, 1188);
    // 9. fc2 + residual -> out (594 tiles on 592 blocks, NT=128)
    hgemm_kernel<0, 0, 128><<<592, 256, SMEM_P128>>>(
        mlph, nullptr, wfc2h, nullptr, fc2b, x2, out, nullptr,
        nullptr, nullptr, nullptr, nullptr, nullptr,
        C_, 4 * C_, C_, 0, 6, 594);
}

// round 15
// speedup vs baseline: 1.0259x; 1.0259x over previous
#include <cuda_runtime.h>
#include <cuda_fp16.h>
#include <math.h>

#define B_   64
#define N_   197
#define C_   768
#define H_   12
#define R_   98
#define K_   99
#define NKEPT_ 98
#define THRK_ 1941
#define ALPHA_ 0.1f
#define EPS_ 1e-5f
#define BH_  (B_*H_)
#define NP_  224

// ---------------- scratch ----------------
__device__ __half   g_attnh[(size_t)BH_*256*NP_];
__device__ float    g_diag[(size_t)BH_*N_];
__device__ float    g_x1  [(size_t)B_*N_*C_];
__device__ float    g_x2  [(size_t)B_*K_*C_];
__device__ int      g_ik  [B_*K_];
__device__ int      g_ie  [B_*R_];
__device__ unsigned g_hh  [(size_t)B_*N_*C_/2];
__device__ unsigned g_hl  [(size_t)B_*N_*C_/2];
__device__ __half   g_wqkvh[(size_t)C_*3*C_];
__device__ __half   g_wqkvl[(size_t)C_*3*C_];
__device__ __half   g_wprojh[(size_t)C_*C_];
__device__ __half   g_wfc1h[(size_t)C_*4*C_];
__device__ __half   g_wfc2h[(size_t)4*C_*C_];
__device__ __half   g_qh[(size_t)BH_*NP_*64];
__device__ __half   g_ql[(size_t)BH_*NP_*64];
__device__ __half   g_kh[(size_t)BH_*NP_*64];
__device__ __half   g_kl[(size_t)BH_*NP_*64];
__device__ __half   g_vh[(size_t)B_*NP_*C_];
__device__ unsigned g_aoh [(size_t)B_*N_*C_/2];
__device__ unsigned g_h2h [(size_t)B_*K_*C_/2];
__device__ unsigned g_mlph[(size_t)B_*K_*4*C_/2];

// ---------------- helpers ----------------
__device__ __forceinline__ unsigned packh2(float a, float b) {
    __half2 h = __floats2half2_rn(a, b);
    return *reinterpret_cast<unsigned*>(&h);
}
__device__ __forceinline__ void splith2(float a, float b, unsigned& hi, unsigned& lo) {
    __half ah = __float2half_rn(a), bh = __float2half_rn(b);
    __half2 h = __halves2half2(ah, bh);
    hi = *reinterpret_cast<unsigned*>(&h);
    lo = packh2(a - __half2float(ah), b - __half2float(bh));
}
__device__ __forceinline__ unsigned sm_u32(const void* p) {
    return (unsigned)__cvta_generic_to_shared(p);
}
__device__ __forceinline__ void ldsm4(unsigned r[4], unsigned a) {
    asm volatile("ldmatrix.sync.aligned.m8n8.x4.shared.b16 {%0,%1,%2,%3}, [%4];"
                 : "=r"(r[0]), "=r"(r[1]), "=r"(r[2]), "=r"(r[3]) : "r"(a));
}
__device__ __forceinline__ void ldsm4t(unsigned r[4], unsigned a) {
    asm volatile("ldmatrix.sync.aligned.m8n8.x4.trans.shared.b16 {%0,%1,%2,%3}, [%4];"
                 : "=r"(r[0]), "=r"(r[1]), "=r"(r[2]), "=r"(r[3]) : "r"(a));
}
__device__ __forceinline__ void mma_f16(float c[4], const unsigned a[4], const unsigned b[2]) {
    asm volatile(
        "mma.sync.aligned.m16n8k16.row.col.f32.f16.f16.f32 "
        "{%0,%1,%2,%3},{%4,%5,%6,%7},{%8,%9},{%0,%1,%2,%3};"
        : "+f"(c[0]), "+f"(c[1]), "+f"(c[2]), "+f"(c[3])
        : "r"(a[0]), "r"(a[1]), "r"(a[2]), "r"(a[3]), "r"(b[0]), "r"(b[1]));
}

// ---------------- fused weight convert ----------------
#define S0_ (768*2304/8)
#define S1_ (S0_ + 768*768/8)
#define S2_ (S1_ + 768*3072/8)
#define S3_ (S2_ + 3072*768/8)
__global__ void cvtw_all(const float* __restrict__ wqkv, const float* __restrict__ wproj,
                         const float* __restrict__ wfc1, const float* __restrict__ wfc2,
                         __half* __restrict__ qkvh, __half* __restrict__ qkvl,
                         __half* __restrict__ projh, __half* __restrict__ fc1h,
                         __half* __restrict__ fc2h)
{
    int i8 = blockIdx.x * 256 + threadIdx.x;
    if (i8 >= S3_) return;
    const float* src; __half* dsth; __half* dstl = nullptr; int base;
    if (i8 < S0_)      { src = wqkv;  dsth = qkvh;  dstl = qkvl; base = 0; }
    else if (i8 < S1_) { src = wproj; dsth = projh; base = S0_; }
    else if (i8 < S2_) { src = wfc1;  dsth = fc1h;  base = S1_; }
    else               { src = wfc2;  dsth = fc2h;  base = S2_; }
    int i = (i8 - base) * 8;
    float4 a = *(const float4*)&src[i];
    float4 b = *(const float4*)&src[i + 4];
    __half2 h[4];
    h[0] = __floats2half2_rn(a.x, a.y); h[1] = __floats2half2_rn(a.z, a.w);
    h[2] = __floats2half2_rn(b.x, b.y); h[3] = __floats2half2_rn(b.z, b.w);
    *(uint4*)&dsth[i] = *(uint4*)h;
    if (dstl) {
        __half2 l[4];
        l[0] = __floats2half2_rn(a.x - __low2float(h[0]), a.y - __high2float(h[0]));
        l[1] = __floats2half2_rn(a.z - __low2float(h[1]), a.w - __high2float(h[1]));
        l[2] = __floats2half2_rn(b.x - __low2float(h[2]), b.y - __high2float(h[2]));
        l[3] = __floats2half2_rn(b.z - __low2float(h[3]), b.w - __high2float(h[3]));
        *(uint4*)&dstl[i] = *(uint4*)l;
    }
}

// ---------------- LayerNorm -> packed fp16 hi(/lo) ----------------
template<int SPLIT>
__global__ void ln_pack_kernel(const float* __restrict__ x, const float* __restrict__ g,
                               const float* __restrict__ bta,
                               unsigned* __restrict__ hi, unsigned* __restrict__ lo)
{
    int row = blockIdx.x;
    const float2* xr = (const float2*)(x + (size_t)row * C_);
    int tid = threadIdx.x;
    float2 v1 = xr[tid];
    float2 v2 = make_float2(0.f, 0.f);
    if (tid < 128) v2 = xr[tid + 256];
    float s = v1.x + v1.y + v2.x + v2.y;
    float ss = v1.x * v1.x + v1.y * v1.y + v2.x * v2.x + v2.y * v2.y;
    for (int off = 16; off; off >>= 1) {
        s  += __shfl_xor_sync(0xffffffffu, s, off);
        ss += __shfl_xor_sync(0xffffffffu, ss, off);
    }
    __shared__ float rs[8], rss[8];
    __shared__ float smean, srstd;
    int w = tid >> 5;
    if ((tid & 31) == 0) { rs[w] = s; rss[w] = ss; }
    __syncthreads();
    if (tid == 0) {
        float S = 0.f, SS = 0.f;
        for (int i = 0; i < 8; i++) { S += rs[i]; SS += rss[i]; }
        float mean = S * (1.f / C_);
        float var = SS * (1.f / C_) - mean * mean;
        smean = mean; srstd = rsqrtf(var + EPS_);
    }
    __syncthreads();
    float mean = smean, rstd = srstd;
    size_t base = (size_t)row * (C_ / 2);
#pragma unroll
    for (int p = 0; p < 2; p++) {
        if (p == 1 && tid >= 128) break;
        int wi = tid + p * 256;
        float2 v = (p == 0) ? v1 : v2;
        int c = wi * 2;
        float a = (v.x - mean) * rstd * g[c] + bta[c];
        float b = (v.y - mean) * rstd * g[c + 1] + bta[c + 1];
        if (SPLIT) { unsigned h, l; splith2(a, b, h, l); hi[base + wi] = h; lo[base + wi] = l; }
        else hi[base + wi] = packh2(a, b);
    }
}

// ---------------- fp16 GEMM: 64xNT tile, direct grid (no tile loop) ----------------
// EPI: 0 = bias+res -> float; 1 = bias+gelu -> packed half; 2 = QK split head-major; 3 = V head-major
#define AST 40
#define ABUF (64 * AST)

template<int SPLIT, int NT>
__device__ __forceinline__ void hg_compute(const __half* buf, const int aoff[2],
                                           const int* boff, float (*acc)[4])
{
    const int BSTc = NT + 8;
    const int BBUFc = 32 * BSTc;
    const int NF = NT / 32;
    const __half* AsH = buf;
    const __half* AsL = buf + ABUF;
    const __half* BsH = buf + ABUF * (1 + SPLIT);
    const __half* BsL = BsH + BBUFc;
#pragma unroll
    for (int s = 0; s < 2; s++) {
        unsigned ah[2][4], al[2][4];
#pragma unroll
        for (int mf = 0; mf < 2; mf++) {
            ldsm4(ah[mf], sm_u32(AsH + aoff[mf] + s * 16));
            if (SPLIT) ldsm4(al[mf], sm_u32(AsL + aoff[mf] + s * 16));
        }
        unsigned bhf[NF][2], blf[NF][2];
#pragma unroll
        for (int p = 0; p < NF / 2; p++) {
            unsigned r[4];
            ldsm4t(r, sm_u32(BsH + boff[p] + s * 16 * BSTc));
            bhf[2*p][0] = r[0]; bhf[2*p][1] = r[1];
            bhf[2*p+1][0] = r[2]; bhf[2*p+1][1] = r[3];
            if (SPLIT) {
                unsigned rl[4];
                ldsm4t(rl, sm_u32(BsL + boff[p] + s * 16 * BSTc));
                blf[2*p][0] = rl[0]; blf[2*p][1] = rl[1];
                blf[2*p+1][0] = rl[2]; blf[2*p+1][1] = rl[3];
            }
        }
#pragma unroll
        for (int mf = 0; mf < 2; mf++)
#pragma unroll
            for (int nf = 0; nf < NF; nf++) {
                mma_f16(acc[mf * NF + nf], ah[mf], bhf[nf]);
                if (SPLIT) {
                    mma_f16(acc[mf * NF + nf], ah[mf], blf[nf]);
                    mma_f16(acc[mf * NF + nf], al[mf], bhf[nf]);
                }
            }
    }
}

template<int SPLIT, int EPI, int NT>
__global__ void __launch_bounds__(256, 2)
hgemm_kernel(const unsigned* __restrict__ Ah, const unsigned* __restrict__ Al,
             const __half* __restrict__ Bh, const __half* __restrict__ Bl,
             const float* __restrict__ bias, const float* __restrict__ res,
             float* __restrict__ Cf, unsigned* __restrict__ Cu,
             unsigned* __restrict__ qh, unsigned* __restrict__ ql,
             unsigned* __restrict__ kh, unsigned* __restrict__ kl,
             unsigned* __restrict__ vh,
             int Nd, int Kd, int ldc, int n0ofs)
{
    extern __shared__ __half sh[];
    const int BSTc = NT + 8;
    const int BBUFc = 32 * BSTc;
    const int NF = NT / 32;
    const int RP = 2048 / NT;
    const int NPASS = NT / 64;
    const int UNIT = (ABUF + BBUFc) * (1 + SPLIT);
    int tid = threadIdx.x, lane = tid & 31, wid = tid >> 5;
    int wm = wid & 1, wn = wid >> 1;
    int g = lane >> 2, tg = lane & 3;
    int m0 = blockIdx.y * 64, n0 = blockIdx.x * NT + n0ofs;
    int Kw = Kd / 2;

    float acc[2 * NF][4];
#pragma unroll
    for (int i = 0; i < 2 * NF; i++)
#pragma unroll
        for (int q = 0; q < 4; q++) acc[i][q] = 0.f;

    int ar = tid >> 2;
    int bkr = tid / (NT / 8), bn8 = (tid % (NT / 8)) * 8;
    const unsigned* ApH = Ah + (size_t)(m0 + ar) * Kw + (tid & 3) * 4;
    const unsigned* ApL = SPLIT ? Al + (size_t)(m0 + ar) * Kw + (tid & 3) * 4 : ApH;
    const __half* BpH = Bh + (size_t)bkr * Nd + n0 + bn8;
    const __half* BpL = SPLIT ? Bl + (size_t)bkr * Nd + n0 + bn8 : BpH;

    int aSts = ar * AST + (tid & 3) * 8;
    int bSts = bkr * BSTc + bn8;

    int aoff[2], boff[NF / 2];
#pragma unroll
    for (int mf = 0; mf < 2; mf++)
        aoff[mf] = (wm * 32 + mf * 16 + (lane & 15)) * AST + (lane >> 4) * 8;
#pragma unroll
    for (int p = 0; p < NF / 2; p++)
        boff[p] = (lane & 15) * BSTc + wn * (NT / 4) + p * 16 + (lane >> 4) * 8;

    uint4 rah, ral, rbh[NPASS], rbl[NPASS];
    rah = *(const uint4*)ApH;
    if (SPLIT) ral = *(const uint4*)ApL;
#pragma unroll
    for (int j = 0; j < NPASS; j++) {
        rbh[j] = *(const uint4*)(BpH + (size_t)(j * RP) * Nd);
        if (SPLIT) rbl[j] = *(const uint4*)(BpL + (size_t)(j * RP) * Nd);
    }
    {
        __half* buf = sh;
        *(uint4*)&buf[aSts] = rah;
        if (SPLIT) *(uint4*)&buf[ABUF + aSts] = ral;
        __half* bb = buf + ABUF * (1 + SPLIT);
#pragma unroll
        for (int j = 0; j < NPASS; j++) {
            *(uint4*)&bb[bSts + j * RP * BSTc] = rbh[j];
            if (SPLIT) *(uint4*)&bb[BBUFc + bSts + j * RP * BSTc] = rbl[j];
        }
    }
    __syncthreads();

    int nit = Kd / 32;
    for (int it = 1; it < nit; it++) {
        rah = *(const uint4*)(ApH + it * 16);
        if (SPLIT) ral = *(const uint4*)(ApL + it * 16);
#pragma unroll
        for (int j = 0; j < NPASS; j++) {
            rbh[j] = *(const uint4*)(BpH + (size_t)(it * 32 + j * RP) * Nd);
            if (SPLIT) rbl[j] = *(const uint4*)(BpL + (size_t)(it * 32 + j * RP) * Nd);
        }
        hg_compute<SPLIT, NT>(sh + ((it - 1) & 1) * UNIT, aoff, boff, acc);
        {
            __half* buf = sh + (it & 1) * UNIT;
            *(uint4*)&buf[aSts] = rah;
            if (SPLIT) *(uint4*)&buf[ABUF + aSts] = ral;
            __half* bb = buf + ABUF * (1 + SPLIT);
#pragma unroll
            for (int j = 0; j < NPASS; j++) {
                *(uint4*)&bb[bSts + j * RP * BSTc] = rbh[j];
                if (SPLIT) *(uint4*)&bb[BBUFc + bSts + j * RP * BSTc] = rbl[j];
            }
        }
        __syncthreads();
    }
    hg_compute<SPLIT, NT>(sh + ((nit - 1) & 1) * UNIT, aoff, boff, acc);

    // epilogue
#pragma unroll
    for (int mf = 0; mf < 2; mf++) {
        int row = m0 + wm * 32 + mf * 16 + g;
#pragma unroll
        for (int nf = 0; nf < NF; nf++) {
            int col = n0 + wn * (NT / 4) + nf * 8 + 2 * tg;
            float b0 = 0.f, b1 = 0.f;
            if (EPI == 0 || EPI == 1) { b0 = bias[col]; b1 = bias[col + 1]; }
#pragma unroll
            for (int half = 0; half < 2; half++) {
                int r = row + half * 8;
                float c0 = acc[mf * NF + nf][half * 2 + 0] + b0;
                float c1 = acc[mf * NF + nf][half * 2 + 1] + b1;
                if (EPI == 0) {
                    size_t base = (size_t)r * ldc + col;
                    float2 rv = *(const float2*)&res[base];
                    float2 ov; ov.x = c0 + rv.x; ov.y = c1 + rv.y;
                    *(float2*)&Cf[base] = ov;
                } else if (EPI == 1) {
                    c0 = 0.5f * c0 * (1.f + erff(c0 * 0.70710678118654752f));
                    c1 = 0.5f * c1 * (1.f + erff(c1 * 0.70710678118654752f));
                    Cu[(size_t)r * (Nd / 2) + col / 2] = packh2(c0, c1);
                } else if (EPI == 2) {
                    int b = r / N_, m = r - b * N_;
                    int part = col >= 768;
                    int rem = col - (part ? 768 : 0);
                    int hd = rem >> 6, d = rem & 63;
                    float s0 = c0, s1 = c1;
                    if (!part) { s0 *= 0.125f; s1 *= 0.125f; }
                    unsigned h, l;
                    splith2(s0, s1, h, l);
                    size_t o = ((size_t)(b * H_ + hd) * NP_ + m) * 32 + (d >> 1);
                    (part ? kh : qh)[o] = h;
                    (part ? kl : ql)[o] = l;
                } else {
                    int b = r / N_, m = r - b * N_;
                    int cv = col - 1536;
                    vh[((size_t)b * NP_ + m) * 384 + (cv >> 1)] = packh2(c0, c1);
                }
            }
        }
    }
}

// ---------------- fused scores + softmax + AV ----------------
#define PSTR 232
__global__ void fsmav_kernel(const __half* __restrict__ qhg, const __half* __restrict__ qlg,
                             const __half* __restrict__ khg, const __half* __restrict__ klg,
                             const __half* __restrict__ vhg,
                             float* __restrict__ diagg, __half* __restrict__ attnh,
                             unsigned* __restrict__ aoh)
{
    extern __shared__ unsigned dsm[];
    unsigned* Qh = dsm;
    unsigned* Ql = Qh + 64 * 36;
    unsigned* Kh = Ql + 64 * 36;
    unsigned* Kl = Kh + 32 * 73;
    unsigned* Ps = Kl + 32 * 73;
    float* red = (float*)(Ps + 64 * (PSTR / 2));

    int bh = blockIdx.x, b = bh / H_, hh = bh % H_;
    int m0 = blockIdx.y * 64;
    int tid = threadIdx.x, lane = tid & 31, wid = tid >> 5;
    int g = lane >> 2, tg = lane & 3;
    int wm = wid & 3, wn = wid >> 2;
    const unsigned* qhw = (const unsigned*)qhg;
    const unsigned* qlw = (const unsigned*)qlg;
    const unsigned* khw = (const unsigned*)khg;
    const unsigned* klw = (const unsigned*)klg;

#pragma unroll
    for (int r = 0; r < 2; r++) {
        int idx = tid + r * 256;
        int row = idx >> 3, w4 = (idx & 7) * 4;
        size_t src = ((size_t)bh * NP_ + m0 + row) * 32 + w4;
        *(uint4*)&Qh[row * 36 + w4] = *(const uint4*)&qhw[src];
        *(uint4*)&Ql[row * 36 + w4] = *(const uint4*)&qlw[src];
    }

    float acc[4][4][4];
#pragma unroll
    for (int c = 0; c < 4; c++)
#pragma unroll
        for (int j = 0; j < 4; j++)
#pragma unroll
            for (int q = 0; q < 4; q++) acc[c][j][q] = 0.f;

    for (int c = 0; c < 4; c++) {
        int n0 = c * 64;
        __syncthreads();
#pragma unroll
        for (int r = 0; r < 2; r++) {
            int idx = tid + r * 256;
            int token = idx >> 3, wp = idx & 7;
            uint4 vh4 = make_uint4(0u, 0u, 0u, 0u), vl4 = make_uint4(0u, 0u, 0u, 0u);
            if (n0 + token < NP_) {
                size_t src = ((size_t)bh * NP_ + n0 + token) * 32 + wp * 4;
                vh4 = *(const uint4*)&khw[src];
                vl4 = *(const uint4*)&klw[src];
            }
            Kh[(wp * 4 + 0) * 73 + token] = vh4.x;
            Kh[(wp * 4 + 1) * 73 + token] = vh4.y;
            Kh[(wp * 4 + 2) * 73 + token] = vh4.z;
            Kh[(wp * 4 + 3) * 73 + token] = vh4.w;
            Kl[(wp * 4 + 0) * 73 + token] = vl4.x;
            Kl[(wp * 4 + 1) * 73 + token] = vl4.y;
            Kl[(wp * 4 + 2) * 73 + token] = vl4.z;
            Kl[(wp * 4 + 3) * 73 + token] = vl4.w;
        }
        __syncthreads();
#pragma unroll
        for (int s = 0; s < 4; s++) {
            int abase = (wm * 16 + g) * 36 + s * 8 + tg;
            unsigned ah[4] = {Qh[abase], Qh[abase + 8 * 36], Qh[abase + 4], Qh[abase + 8 * 36 + 4]};
            unsigned al[4] = {Ql[abase], Ql[abase + 8 * 36], Ql[abase + 4], Ql[abase + 8 * 36 + 4]};
#pragma unroll
            for (int nf = 0; nf < 4; nf++) {
                int n = wn * 32 + nf * 8 + g;
                unsigned bhf[2] = {Kh[(s * 8 + tg) * 73 + n], Kh[(s * 8 + tg + 4) * 73 + n]};
                unsigned blf[2] = {Kl[(s * 8 + tg) * 73 + n], Kl[(s * 8 + tg + 4) * 73 + n]};
                mma_f16(acc[c][nf], ah, bhf);
                mma_f16(acc[c][nf], ah, blf);
                mma_f16(acc[c][nf], al, bhf);
            }
        }
    }

#pragma unroll
    for (int nf = 0; nf < 4; nf++) {
        int col = 192 + wn * 32 + nf * 8 + 2 * tg;
        if (col >= N_)     { acc[3][nf][0] = -1e30f; acc[3][nf][2] = -1e30f; }
        if (col + 1 >= N_) { acc[3][nf][1] = -1e30f; acc[3][nf][3] = -1e30f; }
    }

    int lr0 = wm * 16 + g, lr1 = lr0 + 8;
    float mx0 = -1e30f, mx1 = -1e30f;
#pragma unroll
    for (int c = 0; c < 4; c++)
#pragma unroll
        for (int nf = 0; nf < 4; nf++) {
            mx0 = fmaxf(mx0, fmaxf(acc[c][nf][0], acc[c][nf][1]));
            mx1 = fmaxf(mx1, fmaxf(acc[c][nf][2], acc[c][nf][3]));
        }
    mx0 = fmaxf(mx0, __shfl_xor_sync(0xffffffffu, mx0, 1));
    mx0 = fmaxf(mx0, __shfl_xor_sync(0xffffffffu, mx0, 2));
    mx1 = fmaxf(mx1, __shfl_xor_sync(0xffffffffu, mx1, 1));
    mx1 = fmaxf(mx1, __shfl_xor_sync(0xffffffffu, mx1, 2));
    if (tg == 0) { red[wn * 64 + lr0] = mx0; red[wn * 64 + lr1] = mx1; }
    __syncthreads();
    mx0 = fmaxf(red[0 * 64 + lr0], red[1 * 64 + lr0]);
    mx1 = fmaxf(red[0 * 64 + lr1], red[1 * 64 + lr1]);

    float s0 = 0.f, s1 = 0.f;
#pragma unroll
    for (int c = 0; c < 4; c++)
#pragma unroll
        for (int nf = 0; nf < 4; nf++) {
            float e0 = expf(acc[c][nf][0] - mx0);
            float e1 = expf(acc[c][nf][1] - mx0);
            float e2 = expf(acc[c][nf][2] - mx1);
            float e3 = expf(acc[c][nf][3] - mx1);
            acc[c][nf][0] = e0; acc[c][nf][1] = e1;
            acc[c][nf][2] = e2; acc[c][nf][3] = e3;
            s0 += e0 + e1; s1 += e2 + e3;
        }
    s0 += __shfl_xor_sync(0xffffffffu, s0, 1);
    s0 += __shfl_xor_sync(0xffffffffu, s0, 2);
    s1 += __shfl_xor_sync(0xffffffffu, s1, 1);
    s1 += __shfl_xor_sync(0xffffffffu, s1, 2);
    __syncthreads();
    if (tg == 0) { red[wn * 64 + lr0] = s0; red[wn * 64 + lr1] = s1; }
    __syncthreads();
    float inv0 = 1.f / (red[0 * 64 + lr0] + red[1 * 64 + lr0]);
    float inv1 = 1.f / (red[0 * 64 + lr1] + red[1 * 64 + lr1]);

    int row0 = m0 + lr0, row1 = m0 + lr1;
    unsigned* hout = (unsigned*)attnh;
#pragma unroll
    for (int c = 0; c < 4; c++)
#pragma unroll
        for (int nf = 0; nf < 4; nf++) {
            int col = c * 64 + wn * 32 + nf * 8 + 2 * tg;
            float v00 = acc[c][nf][0] * inv0, v01 = acc[c][nf][1] * inv0;
            float v10 = acc[c][nf][2] * inv1, v11 = acc[c][nf][3] * inv1;
            if (row0 < N_) {
                if (col == row0)          diagg[(size_t)bh * N_ + row0] = v00;
                else if (col + 1 == row0) diagg[(size_t)bh * N_ + row0] = v01;
            }
            if (row1 < N_) {
                if (col == row1)          diagg[(size_t)bh * N_ + row1] = v10;
                else if (col + 1 == row1) diagg[(size_t)bh * N_ + row1] = v11;
            }
            if (col < NP_) {
                unsigned p0 = packh2(v00, v01), p1 = packh2(v10, v11);
                hout[((size_t)bh * 256 + row0) * 112 + col / 2] = p0;
                hout[((size_t)bh * 256 + row1) * 112 + col / 2] = p1;
                Ps[lr0 * (PSTR / 2) + col / 2] = p0;
                Ps[lr1 * (PSTR / 2) + col / 2] = p1;
            }
        }
    __syncthreads();

    // ---- AV from shared probs ----
    const __half* Psh = (const __half*)Ps;
    __half* Vs = (__half*)Kh;
    float acc2[4][4];
#pragma unroll
    for (int i = 0; i < 4; i++)
#pragma unroll
        for (int j = 0; j < 4; j++) acc2[i][j] = 0.f;

    int aoff2 = (wm * 16 + (lane & 15)) * PSTR + (lane >> 4) * 8;
    int boff2[2];
#pragma unroll
    for (int p = 0; p < 2; p++)
        boff2[p] = (lane & 15) * 72 + wn * 32 + p * 16 + (lane >> 4) * 8;

    for (int k0 = 0; k0 < NP_; k0 += 32) {
        __syncthreads();
        {
            int token = tid >> 3, n8 = (tid & 7) * 8;
            const __half* src = vhg + ((size_t)b * NP_ + k0 + token) * C_ + hh * 64 + n8;
            *(uint4*)&Vs[token * 72 + n8] = *(const uint4*)src;
        }
        __syncthreads();
#pragma unroll
        for (int s = 0; s < 2; s++) {
            unsigned ah[4];
            ldsm4(ah, sm_u32(Psh + aoff2 + k0 + s * 16));
#pragma unroll
            for (int p = 0; p < 2; p++) {
                unsigned r[4];
                ldsm4t(r, sm_u32(Vs + boff2[p] + s * 16 * 72));
                unsigned b0[2] = {r[0], r[1]}, b1[2] = {r[2], r[3]};
                mma_f16(acc2[2*p],   ah, b0);
                mma_f16(acc2[2*p+1], ah, b1);
            }
        }
    }
#pragma unroll
    for (int nf = 0; nf < 4; nf++) {
        int col = wn * 32 + nf * 8 + 2 * tg;
#pragma unroll
        for (int hf = 0; hf < 2; hf++) {
            int m = m0 + wm * 16 + g + hf * 8;
            if (m < N_)
                aoh[(size_t)(b * N_ + m) * 384 + (hh * 64 + col) / 2] =
                    packh2(acc2[nf][hf * 2 + 0], acc2[nf][hf * 2 + 1]);
        }
    }
}

// ---------------- selection ----------------
__global__ void select_kernel(const float* __restrict__ diagg, int* __restrict__ ik,
                              int* __restrict__ ie)
{
    __shared__ float diag[196];
    __shared__ int kept[196];
    int b = blockIdx.x, tid = threadIdx.x;
    if (tid < 196) {
        float s = 0.f;
        for (int hh = 0; hh < H_; hh++)
            s += diagg[(size_t)(b * H_ + hh) * N_ + tid + 1];
        diag[tid] = s;
    }
    __syncthreads();
    if (tid < 196) {
        float di = diag[tid];
        int rank = 0;
        for (int j = 0; j < 196; j++) {
            float dj = diag[j];
            rank += (dj > di) || (dj == di && j < tid);
        }
        kept[tid] = (rank < NKEPT_) ? 1 : 0;
    }
    __syncthreads();
    if (tid < 196) {
        int mine = kept[tid];
        int pos = 0;
        for (int j = 0; j < tid; j++) pos += (kept[j] == mine);
        if (mine) ik[b * K_ + 1 + pos] = tid + 1;
        else      ie[b * R_ + pos]     = tid + 1;
    }
    if (tid == 0) ik[b * K_] = 0;
}

// ---------------- propagation ----------------
#define PT_ 38
__global__ void propagate_kernel(const __half* __restrict__ attnh, const float* __restrict__ x1,
                                 const int* __restrict__ ikg, const int* __restrict__ ieg,
                                 float* __restrict__ x2)
{
    extern __shared__ float sm[];
    float* ws = sm;
    float* xe = sm + K_ * R_;
    __shared__ int ik[K_], ie[R_];
    __shared__ int cnt;
    int bh = blockIdx.x;
    int b = bh / H_, hh = bh % H_;
    int tid = threadIdx.x;
    if (tid < K_) ik[tid] = ikg[b * K_ + tid];
    if (tid < R_) ie[tid] = ieg[b * R_ + tid];
    __syncthreads();
    const __half* ablk = attnh + (size_t)bh * 256 * NP_;
    unsigned uv[PT_];
#pragma unroll
    for (int j = 0; j < PT_; j++) {
        int idx = tid + j * 256;
        float w = 0.f;
        if (idx < K_ * R_) {
            int k = idx / R_, e = idx - k * R_;
            w = __half2float(ablk[(size_t)ik[k] * NP_ + ie[e]]);
            ws[idx] = w;
        }
        uv[j] = __float_as_uint(w);
    }
    for (int idx = tid; idx < R_ * 64; idx += 256) {
        int e = idx >> 6, d = idx & 63;
        xe[idx] = x1[(size_t)(b * N_ + ie[e]) * 768 + hh * 64 + d];
    }
    __syncthreads();

    unsigned lo = 0u, hi = 0x3f801000u;
    while (lo < hi) {
        unsigned mid = lo + ((hi - lo + 1) >> 1);
        if (tid == 0) cnt = 0;
        __syncthreads();
        int local = 0;
#pragma unroll
        for (int j = 0; j < PT_; j++) local += (uv[j] >= mid);
        for (int off = 16; off; off >>= 1) local += __shfl_xor_sync(0xffffffffu, local, off);
        if ((tid & 31) == 0) atomicAdd(&cnt, local);
        __syncthreads();
        int c = cnt;
        __syncthreads();
        if (c >= THRK_) lo = mid; else hi = mid - 1;
    }
    float thr = __uint_as_float(lo);

    for (int p = tid; p < K_ * 64; p += 256) {
        int k = p >> 6, d = p & 63;
        const float* wr = ws + k * R_;
        float acc = 0.f;
#pragma unroll 2
        for (int e = 0; e < R_; e++) {
            float wv = wr[e];
            wv = (wv >= thr) ? wv : 0.f;
            acc = fmaf(wv, xe[e * 64 + d], acc);
        }
        x2[(size_t)(b * K_ + k) * 768 + hh * 64 + d] =
            x1[(size_t)(b * N_ + ik[k]) * 768 + hh * 64 + d] + ALPHA_ * acc;
    }
}

// ---------------- host ----------------
extern "C" void kernel_launch(void* const* d_in, const int* in_sizes, int n_in,
                              void* d_out, int out_size)
{
    const float* x     = (const float*)d_in[0];
    const float* n1g   = (const float*)d_in[1];
    const float* n1b   = (const float*)d_in[2];
    const float* qkvw  = (const float*)d_in[3];
    const float* projw = (const float*)d_in[4];
    const float* projb = (const float*)d_in[5];
    const float* n2g   = (const float*)d_in[6];
    const float* n2b   = (const float*)d_in[7];
    const float* fc1w  = (const float*)d_in[8];
    const float* fc1b  = (const float*)d_in[9];
    const float* fc2w  = (const float*)d_in[10];
    const float* fc2b  = (const float*)d_in[11];
    float* out = (float*)d_out;

    float *diagg, *x1, *x2;
    int *ik, *ie;
    unsigned *hh, *hl, *aoh, *h2h, *mlph;
    __half *wqkvh, *wqkvl, *wprojh, *wfc1h, *wfc2h, *attnh, *qh, *ql, *kh, *kl, *vh;
    cudaGetSymbolAddress((void**)&diagg, g_diag);
    cudaGetSymbolAddress((void**)&attnh, g_attnh);
    cudaGetSymbolAddress((void**)&x1,   g_x1);
    cudaGetSymbolAddress((void**)&x2,   g_x2);
    cudaGetSymbolAddress((void**)&ik,   g_ik);
    cudaGetSymbolAddress((void**)&ie,   g_ie);
    cudaGetSymbolAddress((void**)&hh,   g_hh);
    cudaGetSymbolAddress((void**)&hl,   g_hl);
    cudaGetSymbolAddress((void**)&wqkvh, g_wqkvh);
    cudaGetSymbolAddress((void**)&wqkvl, g_wqkvl);
    cudaGetSymbolAddress((void**)&wprojh, g_wprojh);
    cudaGetSymbolAddress((void**)&wfc1h, g_wfc1h);
    cudaGetSymbolAddress((void**)&wfc2h, g_wfc2h);
    cudaGetSymbolAddress((void**)&qh,   g_qh);
    cudaGetSymbolAddress((void**)&ql,   g_ql);
    cudaGetSymbolAddress((void**)&kh,   g_kh);
    cudaGetSymbolAddress((void**)&kl,   g_kl);
    cudaGetSymbolAddress((void**)&vh,   g_vh);
    cudaGetSymbolAddress((void**)&aoh,  g_aoh);
    cudaGetSymbolAddress((void**)&h2h,  g_h2h);
    cudaGetSymbolAddress((void**)&mlph, g_mlph);

    const int PROP_SMEM = (K_ * R_ + R_ * 64) * 4;
    cudaFuncSetAttribute(propagate_kernel, cudaFuncAttributeMaxDynamicSharedMemorySize, PROP_SMEM);
    const int SMEM_P256 = (ABUF + 32 * 264) * 2 * 2;
    const int SMEM_S256 = (ABUF + 32 * 264) * 4 * 2;
    const int SMEM_P128 = (ABUF + 32 * 136) * 2 * 2;
    const int SMEM_FSMAV = (64*36*2 + 32*73*2 + 64*(PSTR/2)) * 4 + 128 * 4;
    cudaFuncSetAttribute(hgemm_kernel<1, 2, 256>, cudaFuncAttributeMaxDynamicSharedMemorySize, SMEM_S256);
    cudaFuncSetAttribute(hgemm_kernel<0, 3, 256>, cudaFuncAttributeMaxDynamicSharedMemorySize, SMEM_P256);
    cudaFuncSetAttribute(hgemm_kernel<0, 0, 256>, cudaFuncAttributeMaxDynamicSharedMemorySize, SMEM_P256);
    cudaFuncSetAttribute(hgemm_kernel<0, 1, 256>, cudaFuncAttributeMaxDynamicSharedMemorySize, SMEM_P256);
    cudaFuncSetAttribute(hgemm_kernel<0, 0, 128>, cudaFuncAttributeMaxDynamicSharedMemorySize, SMEM_P128);
    cudaFuncSetAttribute(fsmav_kernel, cudaFuncAttributeMaxDynamicSharedMemorySize, SMEM_FSMAV);

    // 0. weight conversion
    cvtw_all<<<(S3_ + 255) / 256, 256>>>(qkvw, projw, fc1w, fc2w,
                                         wqkvh, wqkvl, wprojh, wfc1h, wfc2h);
    // 1. LN1
    ln_pack_kernel<1><<<B_ * N_, 256>>>(x, n1g, n1b, hh, hl);
    // 2a. QK (split) -> head-major split-fp16 q/k
    hgemm_kernel<1, 2, 256><<<dim3(6, 197), 256, SMEM_S256>>>(
        hh, hl, wqkvh, wqkvl, nullptr, nullptr, nullptr, nullptr,
        (unsigned*)qh, (unsigned*)ql, (unsigned*)kh, (unsigned*)kl, nullptr, 2304, C_, 0, 0);
    // 2b. V -> head-major fp16
    hgemm_kernel<0, 3, 256><<<dim3(3, 197), 256, SMEM_P256>>>(
        hh, nullptr, wqkvh, nullptr, nullptr, nullptr, nullptr, nullptr,
        nullptr, nullptr, nullptr, nullptr, (unsigned*)vh, 2304, C_, 0, 1536);
    // 3. fused scores + softmax + AV
    fsmav_kernel<<<dim3(BH_, 4), 256, SMEM_FSMAV>>>(qh, ql, kh, kl, vh, diagg, attnh, aoh);
    // 4. proj + bias + residual
    hgemm_kernel<0, 0, 256><<<dim3(3, 197), 256, SMEM_P256>>>(
        aoh, nullptr, wprojh, nullptr, projb, x, x1, nullptr,
        nullptr, nullptr, nullptr, nullptr, nullptr, C_, C_, C_, 0);
    // 5. selection
    select_kernel<<<B_, 256>>>(diagg, ik, ie);
    // 6. propagation
    propagate_kernel<<<BH_, 256, PROP_SMEM>>>(attnh, x1, ik, ie, x2);
    // 7. LN2
    ln_pack_kernel<0><<<B_ * K_, 256>>>(x2, n2g, n2b, h2h, nullptr);
    // 8. fc1 + gelu
    hgemm_kernel<0, 1, 256><<<dim3(12, 99), 256, SMEM_P256>>>(
        h2h, nullptr, wfc1h, nullptr, fc1b, nullptr, nullptr, mlph,
        nullptr, nullptr, nullptr, nullptr, nullptr, 4 * C_, C_, 0, 0);
    // 9. fc2 + residual -> out (NT=128: no 1-block tail wave)
    hgemm_kernel<0, 0, 128><<<dim3(6, 99), 256, SMEM_P128>>>(
        mlph, nullptr, wfc2h, nullptr, fc2b, x2, out, nullptr,
        nullptr, nullptr, nullptr, nullptr, nullptr, C_, 4 * C_, C_, 0);
}

// round 16
// speedup vs baseline: 1.0439x; 1.0175x over previous
#include <cuda_runtime.h>
#include <cuda_fp16.h>
#include <math.h>

#define B_   64
#define N_   197
#define C_   768
#define H_   12
#define R_   98
#define K_   99
#define NKEPT_ 98
#define THRK_ 1941
#define ALPHA_ 0.1f
#define EPS_ 1e-5f
#define BH_  (B_*H_)
#define NP_  224

// ---------------- scratch ----------------
__device__ __half   g_attnh[(size_t)BH_*256*NP_];
__device__ float    g_diag[(size_t)BH_*N_];
__device__ float    g_x1  [(size_t)B_*N_*C_];
__device__ float    g_x2  [(size_t)B_*K_*C_];
__device__ unsigned g_hh  [(size_t)B_*N_*C_/2];
__device__ unsigned g_hl  [(size_t)B_*N_*C_/2];
__device__ __half   g_wqkvh[(size_t)C_*3*C_];
__device__ __half   g_wqkvl[(size_t)C_*3*C_];
__device__ __half   g_wprojh[(size_t)C_*C_];
__device__ __half   g_wfc1h[(size_t)C_*4*C_];
__device__ __half   g_wfc2h[(size_t)4*C_*C_];
__device__ __half   g_qh[(size_t)BH_*NP_*64];
__device__ __half   g_ql[(size_t)BH_*NP_*64];
__device__ __half   g_kh[(size_t)BH_*NP_*64];
__device__ __half   g_kl[(size_t)BH_*NP_*64];
__device__ __half   g_vh[(size_t)B_*NP_*C_];
__device__ unsigned g_aoh [(size_t)B_*N_*C_/2];
__device__ unsigned g_h2h [(size_t)B_*K_*C_/2];
__device__ unsigned g_mlph[(size_t)B_*K_*4*C_/2];

// ---------------- helpers ----------------
__device__ __forceinline__ unsigned packh2(float a, float b) {
    __half2 h = __floats2half2_rn(a, b);
    return *reinterpret_cast<unsigned*>(&h);
}
__device__ __forceinline__ void splith2(float a, float b, unsigned& hi, unsigned& lo) {
    __half ah = __float2half_rn(a), bh = __float2half_rn(b);
    __half2 h = __halves2half2(ah, bh);
    hi = *reinterpret_cast<unsigned*>(&h);
    lo = packh2(a - __half2float(ah), b - __half2float(bh));
}
__device__ __forceinline__ unsigned sm_u32(const void* p) {
    return (unsigned)__cvta_generic_to_shared(p);
}
__device__ __forceinline__ void ldsm4(unsigned r[4], unsigned a) {
    asm volatile("ldmatrix.sync.aligned.m8n8.x4.shared.b16 {%0,%1,%2,%3}, [%4];"
                 : "=r"(r[0]), "=r"(r[1]), "=r"(r[2]), "=r"(r[3]) : "r"(a));
}
__device__ __forceinline__ void ldsm4t(unsigned r[4], unsigned a) {
    asm volatile("ldmatrix.sync.aligned.m8n8.x4.trans.shared.b16 {%0,%1,%2,%3}, [%4];"
                 : "=r"(r[0]), "=r"(r[1]), "=r"(r[2]), "=r"(r[3]) : "r"(a));
}
__device__ __forceinline__ void mma_f16(float c[4], const unsigned a[4], const unsigned b[2]) {
    asm volatile(
        "mma.sync.aligned.m16n8k16.row.col.f32.f16.f16.f32 "
        "{%0,%1,%2,%3},{%4,%5,%6,%7},{%8,%9},{%0,%1,%2,%3};"
        : "+f"(c[0]), "+f"(c[1]), "+f"(c[2]), "+f"(c[3])
        : "r"(a[0]), "r"(a[1]), "r"(a[2]), "r"(a[3]), "r"(b[0]), "r"(b[1]));
}
__device__ __forceinline__ void cpa16(unsigned dst, const void* src) {
    asm volatile("cp.async.cg.shared.global [%0], [%1], 16;" :: "r"(dst), "l"(src));
}

// ---------------- fused weight convert ----------------
#define S0_ (768*2304/8)
#define S1_ (S0_ + 768*768/8)
#define S2_ (S1_ + 768*3072/8)
#define S3_ (S2_ + 3072*768/8)
__global__ void cvtw_all(const float* __restrict__ wqkv, const float* __restrict__ wproj,
                         const float* __restrict__ wfc1, const float* __restrict__ wfc2,
                         __half* __restrict__ qkvh, __half* __restrict__ qkvl,
                         __half* __restrict__ projh, __half* __restrict__ fc1h,
                         __half* __restrict__ fc2h)
{
    int i8 = blockIdx.x * 256 + threadIdx.x;
    if (i8 >= S3_) return;
    const float* src; __half* dsth; __half* dstl = nullptr; int base;
    if (i8 < S0_)      { src = wqkv;  dsth = qkvh;  dstl = qkvl; base = 0; }
    else if (i8 < S1_) { src = wproj; dsth = projh; base = S0_; }
    else if (i8 < S2_) { src = wfc1;  dsth = fc1h;  base = S1_; }
    else               { src = wfc2;  dsth = fc2h;  base = S2_; }
    int i = (i8 - base) * 8;
    float4 a = *(const float4*)&src[i];
    float4 b = *(const float4*)&src[i + 4];
    __half2 h[4];
    h[0] = __floats2half2_rn(a.x, a.y); h[1] = __floats2half2_rn(a.z, a.w);
    h[2] = __floats2half2_rn(b.x, b.y); h[3] = __floats2half2_rn(b.z, b.w);
    *(uint4*)&dsth[i] = *(uint4*)h;
    if (dstl && (i % 2304) < 1536) {     // lo only needed for QK columns
        __half2 l[4];
        l[0] = __floats2half2_rn(a.x - __low2float(h[0]), a.y - __high2float(h[0]));
        l[1] = __floats2half2_rn(a.z - __low2float(h[1]), a.w - __high2float(h[1]));
        l[2] = __floats2half2_rn(b.x - __low2float(h[2]), b.y - __high2float(h[2]));
        l[3] = __floats2half2_rn(b.z - __low2float(h[3]), b.w - __high2float(h[3]));
        *(uint4*)&dstl[i] = *(uint4*)l;
    }
}

// ---------------- LayerNorm -> packed fp16 hi(/lo) ----------------
template<int SPLIT>
__global__ void ln_pack_kernel(const float* __restrict__ x, const float* __restrict__ g,
                               const float* __restrict__ bta,
                               unsigned* __restrict__ hi, unsigned* __restrict__ lo)
{
    int row = blockIdx.x;
    const float2* xr = (const float2*)(x + (size_t)row * C_);
    int tid = threadIdx.x;
    float2 v1 = xr[tid];
    float2 v2 = make_float2(0.f, 0.f);
    if (tid < 128) v2 = xr[tid + 256];
    float s = v1.x + v1.y + v2.x + v2.y;
    float ss = v1.x * v1.x + v1.y * v1.y + v2.x * v2.x + v2.y * v2.y;
    for (int off = 16; off; off >>= 1) {
        s  += __shfl_xor_sync(0xffffffffu, s, off);
        ss += __shfl_xor_sync(0xffffffffu, ss, off);
    }
    __shared__ float rs[8], rss[8];
    __shared__ float smean, srstd;
    int w = tid >> 5;
    if ((tid & 31) == 0) { rs[w] = s; rss[w] = ss; }
    __syncthreads();
    if (tid == 0) {
        float S = 0.f, SS = 0.f;
        for (int i = 0; i < 8; i++) { S += rs[i]; SS += rss[i]; }
        float mean = S * (1.f / C_);
        float var = SS * (1.f / C_) - mean * mean;
        smean = mean; srstd = rsqrtf(var + EPS_);
    }
    __syncthreads();
    float mean = smean, rstd = srstd;
    size_t base = (size_t)row * (C_ / 2);
#pragma unroll
    for (int p = 0; p < 2; p++) {
        if (p == 1 && tid >= 128) break;
        int wi = tid + p * 256;
        float2 v = (p == 0) ? v1 : v2;
        int c = wi * 2;
        float a = (v.x - mean) * rstd * g[c] + bta[c];
        float b = (v.y - mean) * rstd * g[c + 1] + bta[c + 1];
        if (SPLIT) { unsigned h, l; splith2(a, b, h, l); hi[base + wi] = h; lo[base + wi] = l; }
        else hi[base + wi] = packh2(a, b);
    }
}

// ---------------- fp16 GEMM: 64xNT tile ----------------
// SPLIT=1: 2-stage register-staged; SPLIT=0: 3-stage cp.async
// EPI: 0 = bias+res -> float; 1 = bias+gelu -> packed half; 2 = QK split head-major; 3 = V head-major
#define AST 40
#define ABUF (64 * AST)

template<int SPLIT, int NT>
__device__ __forceinline__ void hg_compute(const __half* buf, const int aoff[2],
                                           const int* boff, float (*acc)[4])
{
    const int BSTc = NT + 8;
    const int BBUFc = 32 * BSTc;
    const int NF = NT / 32;
    const __half* AsH = buf;
    const __half* AsL = buf + ABUF;
    const __half* BsH = buf + ABUF * (1 + SPLIT);
    const __half* BsL = BsH + BBUFc;
#pragma unroll
    for (int s = 0; s < 2; s++) {
        unsigned ah[2][4], al[2][4];
#pragma unroll
        for (int mf = 0; mf < 2; mf++) {
            ldsm4(ah[mf], sm_u32(AsH + aoff[mf] + s * 16));
            if (SPLIT) ldsm4(al[mf], sm_u32(AsL + aoff[mf] + s * 16));
        }
        unsigned bhf[NF][2], blf[NF][2];
#pragma unroll
        for (int p = 0; p < NF / 2; p++) {
            unsigned r[4];
            ldsm4t(r, sm_u32(BsH + boff[p] + s * 16 * BSTc));
            bhf[2*p][0] = r[0]; bhf[2*p][1] = r[1];
            bhf[2*p+1][0] = r[2]; bhf[2*p+1][1] = r[3];
            if (SPLIT) {
                unsigned rl[4];
                ldsm4t(rl, sm_u32(BsL + boff[p] + s * 16 * BSTc));
                blf[2*p][0] = rl[0]; blf[2*p][1] = rl[1];
                blf[2*p+1][0] = rl[2]; blf[2*p+1][1] = rl[3];
            }
        }
#pragma unroll
        for (int mf = 0; mf < 2; mf++)
#pragma unroll
            for (int nf = 0; nf < NF; nf++) {
                mma_f16(acc[mf * NF + nf], ah[mf], bhf[nf]);
                if (SPLIT) {
                    mma_f16(acc[mf * NF + nf], ah[mf], blf[nf]);
                    mma_f16(acc[mf * NF + nf], al[mf], bhf[nf]);
                }
            }
    }
}

template<int SPLIT, int EPI, int NT>
__global__ void __launch_bounds__(256, 2)
hgemm_kernel(const unsigned* __restrict__ Ah, const unsigned* __restrict__ Al,
             const __half* __restrict__ Bh, const __half* __restrict__ Bl,
             const float* __restrict__ bias, const float* __restrict__ res,
             float* __restrict__ Cf, unsigned* __restrict__ Cu,
             unsigned* __restrict__ qh, unsigned* __restrict__ ql,
             unsigned* __restrict__ kh, unsigned* __restrict__ kl,
             unsigned* __restrict__ vh,
             int Nd, int Kd, int ldc, int n0ofs)
{
    extern __shared__ __half sh[];
    const int BSTc = NT + 8;
    const int BBUFc = 32 * BSTc;
    const int NF = NT / 32;
    const int RP = 2048 / NT;
    const int NPASS = NT / 64;
    int tid = threadIdx.x, lane = tid & 31, wid = tid >> 5;
    int wm = wid & 1, wn = wid >> 1;
    int g = lane >> 2, tg = lane & 3;
    int m0 = blockIdx.y * 64, n0 = blockIdx.x * NT + n0ofs;
    int Kw = Kd / 2;

    float acc[2 * NF][4];
#pragma unroll
    for (int i = 0; i < 2 * NF; i++)
#pragma unroll
        for (int q = 0; q < 4; q++) acc[i][q] = 0.f;

    int ar = tid >> 2;
    int bkr = tid / (NT / 8), bn8 = (tid % (NT / 8)) * 8;
    const unsigned* ApH = Ah + (size_t)(m0 + ar) * Kw + (tid & 3) * 4;
    const unsigned* ApL = SPLIT ? Al + (size_t)(m0 + ar) * Kw + (tid & 3) * 4 : ApH;
    const __half* BpH = Bh + (size_t)bkr * Nd + n0 + bn8;
    const __half* BpL = SPLIT ? Bl + (size_t)bkr * Nd + n0 + bn8 : BpH;

    int aSts = ar * AST + (tid & 3) * 8;
    int bSts = bkr * BSTc + bn8;

    int aoff[2], boff[NF / 2];
#pragma unroll
    for (int mf = 0; mf < 2; mf++)
        aoff[mf] = (wm * 32 + mf * 16 + (lane & 15)) * AST + (lane >> 4) * 8;
#pragma unroll
    for (int p = 0; p < NF / 2; p++)
        boff[p] = (lane & 15) * BSTc + wn * (NT / 4) + p * 16 + (lane >> 4) * 8;

    int nit = Kd / 32;

    if (SPLIT) {
        const int UNIT = (ABUF + BBUFc) * 2;
        uint4 rah, ral, rbh[NPASS], rbl[NPASS];
        rah = *(const uint4*)ApH;
        ral = *(const uint4*)ApL;
#pragma unroll
        for (int j = 0; j < NPASS; j++) {
            rbh[j] = *(const uint4*)(BpH + (size_t)(j * RP) * Nd);
            rbl[j] = *(const uint4*)(BpL + (size_t)(j * RP) * Nd);
        }
        {
            __half* buf = sh;
            *(uint4*)&buf[aSts] = rah;
            *(uint4*)&buf[ABUF + aSts] = ral;
            __half* bb = buf + ABUF * 2;
#pragma unroll
            for (int j = 0; j < NPASS; j++) {
                *(uint4*)&bb[bSts + j * RP * BSTc] = rbh[j];
                *(uint4*)&bb[BBUFc + bSts + j * RP * BSTc] = rbl[j];
            }
        }
        __syncthreads();
        for (int it = 1; it < nit; it++) {
            rah = *(const uint4*)(ApH + it * 16);
            ral = *(const uint4*)(ApL + it * 16);
#pragma unroll
            for (int j = 0; j < NPASS; j++) {
                rbh[j] = *(const uint4*)(BpH + (size_t)(it * 32 + j * RP) * Nd);
                rbl[j] = *(const uint4*)(BpL + (size_t)(it * 32 + j * RP) * Nd);
            }
            hg_compute<1, NT>(sh + ((it - 1) & 1) * UNIT, aoff, boff, acc);
            {
                __half* buf = sh + (it & 1) * UNIT;
                *(uint4*)&buf[aSts] = rah;
                *(uint4*)&buf[ABUF + aSts] = ral;
                __half* bb = buf + ABUF * 2;
#pragma unroll
                for (int j = 0; j < NPASS; j++) {
                    *(uint4*)&bb[bSts + j * RP * BSTc] = rbh[j];
                    *(uint4*)&bb[BBUFc + bSts + j * RP * BSTc] = rbl[j];
                }
            }
            __syncthreads();
        }
        hg_compute<1, NT>(sh + ((nit - 1) & 1) * UNIT, aoff, boff, acc);
    } else {
        const int UNITP = ABUF + BBUFc;
        // prologue: prefetch stages for k=0,1
#pragma unroll
        for (int st = 0; st < 2; st++) {
            __half* buf = sh + st * UNITP;
            cpa16(sm_u32(buf + aSts), ApH + st * 16);
            __half* bb = buf + ABUF;
#pragma unroll
            for (int j = 0; j < NPASS; j++)
                cpa16(sm_u32(bb + bSts + j * RP * BSTc), BpH + (size_t)(st * 32 + j * RP) * Nd);
            asm volatile("cp.async.commit_group;");
        }
        for (int it = 0; it < nit; it++) {
            asm volatile("cp.async.wait_group 1;");
            __syncthreads();
            int kp = it + 2;
            if (kp < nit) {
                __half* buf = sh + (kp % 3) * UNITP;
                cpa16(sm_u32(buf + aSts), ApH + kp * 16);
                __half* bb = buf + ABUF;
#pragma unroll
                for (int j = 0; j < NPASS; j++)
                    cpa16(sm_u32(bb + bSts + j * RP * BSTc), BpH + (size_t)(kp * 32 + j * RP) * Nd);
            }
            asm volatile("cp.async.commit_group;");
            hg_compute<0, NT>(sh + (it % 3) * UNITP, aoff, boff, acc);
        }
    }

    // epilogue
#pragma unroll
    for (int mf = 0; mf < 2; mf++) {
        int row = m0 + wm * 32 + mf * 16 + g;
#pragma unroll
        for (int nf = 0; nf < NF; nf++) {
            int col = n0 + wn * (NT / 4) + nf * 8 + 2 * tg;
            float b0 = 0.f, b1 = 0.f;
            if (EPI == 0 || EPI == 1) { b0 = bias[col]; b1 = bias[col + 1]; }
#pragma unroll
            for (int half = 0; half < 2; half++) {
                int r = row + half * 8;
                float c0 = acc[mf * NF + nf][half * 2 + 0] + b0;
                float c1 = acc[mf * NF + nf][half * 2 + 1] + b1;
                if (EPI == 0) {
                    size_t base = (size_t)r * ldc + col;
                    float2 rv = *(const float2*)&res[base];
                    float2 ov; ov.x = c0 + rv.x; ov.y = c1 + rv.y;
                    *(float2*)&Cf[base] = ov;
                } else if (EPI == 1) {
                    c0 = 0.5f * c0 * (1.f + erff(c0 * 0.70710678118654752f));
                    c1 = 0.5f * c1 * (1.f + erff(c1 * 0.70710678118654752f));
                    Cu[(size_t)r * (Nd / 2) + col / 2] = packh2(c0, c1);
                } else if (EPI == 2) {
                    int b = r / N_, m = r - b * N_;
                    int part = col >= 768;
                    int rem = col - (part ? 768 : 0);
                    int hd = rem >> 6, d = rem & 63;
                    float s0 = c0, s1 = c1;
                    if (!part) { s0 *= 0.125f; s1 *= 0.125f; }
                    unsigned h, l;
                    splith2(s0, s1, h, l);
                    size_t o = ((size_t)(b * H_ + hd) * NP_ + m) * 32 + (d >> 1);
                    (part ? kh : qh)[o] = h;
                    (part ? kl : ql)[o] = l;
                } else {
                    int b = r / N_, m = r - b * N_;
                    int cv = col - 1536;
                    vh[((size_t)b * NP_ + m) * 384 + (cv >> 1)] = packh2(c0, c1);
                }
            }
        }
    }
}

// ---------------- fused scores + softmax + AV (all ldmatrix) ----------------
#define PSTR 232
__global__ void fsmav_kernel(const __half* __restrict__ qhg, const __half* __restrict__ qlg,
                             const __half* __restrict__ khg, const __half* __restrict__ klg,
                             const __half* __restrict__ vhg,
                             float* __restrict__ diagg, __half* __restrict__ attnh,
                             unsigned* __restrict__ aoh)
{
    extern __shared__ unsigned dsm[];
    unsigned* Qh = dsm;                        // 64*36 words, [row][kword]
    unsigned* Ql = Qh + 64 * 36;
    unsigned* Kh = Ql + 64 * 36;               // 64*36 words, [token][dword]
    unsigned* Kl = Kh + 64 * 36;
    unsigned* Ps = Kl + 64 * 36;               // 64*(PSTR/2)
    float* red = (float*)(Ps + 64 * (PSTR / 2));

    int bh = blockIdx.x, b = bh / H_, hh = bh % H_;
    int m0 = blockIdx.y * 64;
    int tid = threadIdx.x, lane = tid & 31, wid = tid >> 5;
    int g = lane >> 2, tg = lane & 3;
    int wm = wid & 3, wn = wid >> 2;
    const unsigned* qhw = (const unsigned*)qhg;
    const unsigned* qlw = (const unsigned*)qlg;
    const unsigned* khw = (const unsigned*)khg;
    const unsigned* klw = (const unsigned*)klg;
    const uint4 z4 = make_uint4(0u, 0u, 0u, 0u);

    // Q tile [64 rows][32 words], zero-pad rows >= NP_
#pragma unroll
    for (int r = 0; r < 2; r++) {
        int idx = tid + r * 256;
        int row = idx >> 3, w4 = (idx & 7) * 4;
        uint4 qh4 = z4, ql4 = z4;
        if (m0 + row < NP_) {
            size_t src = ((size_t)bh * NP_ + m0 + row) * 32 + w4;
            qh4 = *(const uint4*)&qhw[src];
            ql4 = *(const uint4*)&qlw[src];
        }
        *(uint4*)&Qh[row * 36 + w4] = qh4;
        *(uint4*)&Ql[row * 36 + w4] = ql4;
    }

    // fragment offsets (in halves; strides 72)
    int aoffQ = (wm * 16 + (lane & 15)) * 72 + (lane >> 4) * 8;
    int boffS[2];
#pragma unroll
    for (int p = 0; p < 2; p++)
        boffS[p] = (wn * 32 + p * 16 + (lane & 15)) * 72 + (lane >> 4) * 8;

    float acc[4][4][4];
#pragma unroll
    for (int c = 0; c < 4; c++)
#pragma unroll
        for (int j = 0; j < 4; j++)
#pragma unroll
            for (int q = 0; q < 4; q++) acc[c][j][q] = 0.f;

    const __half* Qhh = (const __half*)Qh;
    const __half* Qlh = (const __half*)Ql;
    const __half* Khh = (const __half*)Kh;
    const __half* Klh = (const __half*)Kl;

    for (int c = 0; c < 4; c++) {
        int n0 = c * 64;
        __syncthreads();
        // K tile [64 tokens][32 words], zero-pad tokens >= NP_
#pragma unroll
        for (int r = 0; r < 2; r++) {
            int idx = tid + r * 256;
            int row = idx >> 3, w4 = (idx & 7) * 4;
            uint4 kh4 = z4, kl4 = z4;
            if (n0 + row < NP_) {
                size_t src = ((size_t)bh * NP_ + n0 + row) * 32 + w4;
                kh4 = *(const uint4*)&khw[src];
                kl4 = *(const uint4*)&klw[src];
            }
            *(uint4*)&Kh[row * 36 + w4] = kh4;
            *(uint4*)&Kl[row * 36 + w4] = kl4;
        }
        __syncthreads();
#pragma unroll
        for (int s = 0; s < 4; s++) {
            unsigned ah[4], al[4];
            ldsm4(ah, sm_u32(Qhh + aoffQ + s * 16));
            ldsm4(al, sm_u32(Qlh + aoffQ + s * 16));
#pragma unroll
            for (int p = 0; p < 2; p++) {
                unsigned rh[4], rl[4];
                ldsm4(rh, sm_u32(Khh + boffS[p] + s * 16));
                ldsm4(rl, sm_u32(Klh + boffS[p] + s * 16));
                unsigned bh0[2] = {rh[0], rh[2]}, bh1[2] = {rh[1], rh[3]};
                unsigned bl0[2] = {rl[0], rl[2]}, bl1[2] = {rl[1], rl[3]};
                mma_f16(acc[c][2*p],   ah, bh0);
                mma_f16(acc[c][2*p],   ah, bl0);
                mma_f16(acc[c][2*p],   al, bh0);
                mma_f16(acc[c][2*p+1], ah, bh1);
                mma_f16(acc[c][2*p+1], ah, bl1);
                mma_f16(acc[c][2*p+1], al, bh1);
            }
        }
    }

    // mask invalid columns (chunk 3 covers cols 192..255)
#pragma unroll
    for (int nf = 0; nf < 4; nf++) {
        int col = 192 + wn * 32 + nf * 8 + 2 * tg;
        if (col >= N_)     { acc[3][nf][0] = -1e30f; acc[3][nf][2] = -1e30f; }
        if (col + 1 >= N_) { acc[3][nf][1] = -1e30f; acc[3][nf][3] = -1e30f; }
    }

    int lr0 = wm * 16 + g, lr1 = lr0 + 8;
    float mx0 = -1e30f, mx1 = -1e30f;
#pragma unroll
    for (int c = 0; c < 4; c++)
#pragma unroll
        for (int nf = 0; nf < 4; nf++) {
            mx0 = fmaxf(mx0, fmaxf(acc[c][nf][0], acc[c][nf][1]));
            mx1 = fmaxf(mx1, fmaxf(acc[c][nf][2], acc[c][nf][3]));
        }
    mx0 = fmaxf(mx0, __shfl_xor_sync(0xffffffffu, mx0, 1));
    mx0 = fmaxf(mx0, __shfl_xor_sync(0xffffffffu, mx0, 2));
    mx1 = fmaxf(mx1, __shfl_xor_sync(0xffffffffu, mx1, 1));
    mx1 = fmaxf(mx1, __shfl_xor_sync(0xffffffffu, mx1, 2));
    if (tg == 0) { red[wn * 64 + lr0] = mx0; red[wn * 64 + lr1] = mx1; }
    __syncthreads();
    mx0 = fmaxf(red[0 * 64 + lr0], red[1 * 64 + lr0]);
    mx1 = fmaxf(red[0 * 64 + lr1], red[1 * 64 + lr1]);

    float s0 = 0.f, s1 = 0.f;
#pragma unroll
    for (int c = 0; c < 4; c++)
#pragma unroll
        for (int nf = 0; nf < 4; nf++) {
            float e0 = expf(acc[c][nf][0] - mx0);
            float e1 = expf(acc[c][nf][1] - mx0);
            float e2 = expf(acc[c][nf][2] - mx1);
            float e3 = expf(acc[c][nf][3] - mx1);
            acc[c][nf][0] = e0; acc[c][nf][1] = e1;
            acc[c][nf][2] = e2; acc[c][nf][3] = e3;
            s0 += e0 + e1; s1 += e2 + e3;
        }
    s0 += __shfl_xor_sync(0xffffffffu, s0, 1);
    s0 += __shfl_xor_sync(0xffffffffu, s0, 2);
    s1 += __shfl_xor_sync(0xffffffffu, s1, 1);
    s1 += __shfl_xor_sync(0xffffffffu, s1, 2);
    __syncthreads();
    if (tg == 0) { red[wn * 64 + lr0] = s0; red[wn * 64 + lr1] = s1; }
    __syncthreads();
    float inv0 = 1.f / (red[0 * 64 + lr0] + red[1 * 64 + lr0]);
    float inv1 = 1.f / (red[0 * 64 + lr1] + red[1 * 64 + lr1]);

    int row0 = m0 + lr0, row1 = m0 + lr1;
    unsigned* hout = (unsigned*)attnh;
#pragma unroll
    for (int c = 0; c < 4; c++)
#pragma unroll
        for (int nf = 0; nf < 4; nf++) {
            int col = c * 64 + wn * 32 + nf * 8 + 2 * tg;
            float v00 = acc[c][nf][0] * inv0, v01 = acc[c][nf][1] * inv0;
            float v10 = acc[c][nf][2] * inv1, v11 = acc[c][nf][3] * inv1;
            if (row0 < N_) {
                if (col == row0)          diagg[(size_t)bh * N_ + row0] = v00;
                else if (col + 1 == row0) diagg[(size_t)bh * N_ + row0] = v01;
            }
            if (row1 < N_) {
                if (col == row1)          diagg[(size_t)bh * N_ + row1] = v10;
                else if (col + 1 == row1) diagg[(size_t)bh * N_ + row1] = v11;
            }
            if (col < NP_) {
                unsigned p0 = packh2(v00, v01), p1 = packh2(v10, v11);
                hout[((size_t)bh * 256 + row0) * 112 + col / 2] = p0;
                hout[((size_t)bh * 256 + row1) * 112 + col / 2] = p1;
                Ps[lr0 * (PSTR / 2) + col / 2] = p0;
                Ps[lr1 * (PSTR / 2) + col / 2] = p1;
            }
        }
    __syncthreads();

    // ---- AV from shared probs ----
    const __half* Psh = (const __half*)Ps;
    __half* Vs = (__half*)Kh;          // reuse K area: 32x72 halves
    float acc2[4][4];
#pragma unroll
    for (int i = 0; i < 4; i++)
#pragma unroll
        for (int j = 0; j < 4; j++) acc2[i][j] = 0.f;

    int aoff2 = (wm * 16 + (lane & 15)) * PSTR + (lane >> 4) * 8;
    int boff2[2];
#pragma unroll
    for (int p = 0; p < 2; p++)
        boff2[p] = (lane & 15) * 72 + wn * 32 + p * 16 + (lane >> 4) * 8;

    for (int k0 = 0; k0 < NP_; k0 += 32) {
        __syncthreads();
        {
            int token = tid >> 3, n8 = (tid & 7) * 8;
            const __half* src = vhg + ((size_t)b * NP_ + k0 + token) * C_ + hh * 64 + n8;
            *(uint4*)&Vs[token * 72 + n8] = *(const uint4*)src;
        }
        __syncthreads();
#pragma unroll
        for (int s = 0; s < 2; s++) {
            unsigned ah[4];
            ldsm4(ah, sm_u32(Psh + aoff2 + k0 + s * 16));
#pragma unroll
            for (int p = 0; p < 2; p++) {
                unsigned r[4];
                ldsm4t(r, sm_u32(Vs + boff2[p] + s * 16 * 72));
                unsigned b0[2] = {r[0], r[1]}, b1[2] = {r[2], r[3]};
                mma_f16(acc2[2*p],   ah, b0);
                mma_f16(acc2[2*p+1], ah, b1);
            }
        }
    }
#pragma unroll
    for (int nf = 0; nf < 4; nf++) {
        int col = wn * 32 + nf * 8 + 2 * tg;
#pragma unroll
        for (int hf = 0; hf < 2; hf++) {
            int m = m0 + wm * 16 + g + hf * 8;
            if (m < N_)
                aoh[(size_t)(b * N_ + m) * 384 + (hh * 64 + col) / 2] =
                    packh2(acc2[nf][hf * 2 + 0], acc2[nf][hf * 2 + 1]);
        }
    }
}

// ---------------- propagation with fused selection ----------------
#define PT_ 38
__global__ void propagate_kernel(const float* __restrict__ diagg,
                                 const __half* __restrict__ attnh,
                                 const float* __restrict__ x1,
                                 float* __restrict__ x2)
{
    extern __shared__ float sm[];
    float* ws = sm;
    float* xe = sm + K_ * R_;
    __shared__ float diag[196];
    __shared__ int kept[196];
    __shared__ int ik[K_], ie[R_];
    __shared__ int cnt;
    int bh = blockIdx.x;
    int b = bh / H_, hh = bh % H_;
    int tid = threadIdx.x;

    // inlined selection for batch b (stable argsort semantics, identical to reference)
    if (tid < 196) {
        float s = 0.f;
#pragma unroll
        for (int h2 = 0; h2 < H_; h2++)
            s += diagg[(size_t)(b * H_ + h2) * N_ + tid + 1];
        diag[tid] = s;
    }
    __syncthreads();
    if (tid < 196) {
        float di = diag[tid];
        int rank = 0;
        for (int j = 0; j < 196; j++) {
            float dj = diag[j];
            rank += (dj > di) || (dj == di && j < tid);
        }
        kept[tid] = (rank < NKEPT_) ? 1 : 0;
    }
    __syncthreads();
    if (tid < 196) {
        int mine = kept[tid];
        int pos = 0;
        for (int j = 0; j < tid; j++) pos += (kept[j] == mine);
        if (mine) ik[1 + pos] = tid + 1;
        else      ie[pos]     = tid + 1;
    }
    if (tid == 0) ik[0] = 0;
    __syncthreads();

    const __half* ablk = attnh + (size_t)bh * 256 * NP_;
    unsigned uv[PT_];
#pragma unroll
    for (int j = 0; j < PT_; j++) {
        int idx = tid + j * 256;
        float w = 0.f;
        if (idx < K_ * R_) {
            int k = idx / R_, e = idx - k * R_;
            w = __half2float(ablk[(size_t)ik[k] * NP_ + ie[e]]);
            ws[idx] = w;
        }
        uv[j] = __float_as_uint(w);
    }
    for (int idx = tid; idx < R_ * 64; idx += 256) {
        int e = idx >> 6, d = idx & 63;
        xe[idx] = x1[(size_t)(b * N_ + ie[e]) * 768 + hh * 64 + d];
    }
    __syncthreads();

    unsigned lo = 0u, hi = 0x3f801000u;
    while (lo < hi) {
        unsigned mid = lo + ((hi - lo + 1) >> 1);
        if (tid == 0) cnt = 0;
        __syncthreads();
        int local = 0;
#pragma unroll
        for (int j = 0; j < PT_; j++) local += (uv[j] >= mid);
        for (int off = 16; off; off >>= 1) local += __shfl_xor_sync(0xffffffffu, local, off);
        if ((tid & 31) == 0) atomicAdd(&cnt, local);
        __syncthreads();
        int c = cnt;
        __syncthreads();
        if (c >= THRK_) lo = mid; else hi = mid - 1;
    }
    float thr = __uint_as_float(lo);

    for (int p = tid; p < K_ * 64; p += 256) {
        int k = p >> 6, d = p & 63;
        const float* wr = ws + k * R_;
        float acc = 0.f;
#pragma unroll 2
        for (int e = 0; e < R_; e++) {
            float wv = wr[e];
            wv = (wv >= thr) ? wv : 0.f;
            acc = fmaf(wv, xe[e * 64 + d], acc);
        }
        x2[(size_t)(b * K_ + k) * 768 + hh * 64 + d] =
            x1[(size_t)(b * N_ + ik[k]) * 768 + hh * 64 + d] + ALPHA_ * acc;
    }
}

// ---------------- host ----------------
extern "C" void kernel_launch(void* const* d_in, const int* in_sizes, int n_in,
                              void* d_out, int out_size)
{
    const float* x     = (const float*)d_in[0];
    const float* n1g   = (const float*)d_in[1];
    const float* n1b   = (const float*)d_in[2];
    const float* qkvw  = (const float*)d_in[3];
    const float* projw = (const float*)d_in[4];
    const float* projb = (const float*)d_in[5];
    const float* n2g   = (const float*)d_in[6];
    const float* n2b   = (const float*)d_in[7];
    const float* fc1w  = (const float*)d_in[8];
    const float* fc1b  = (const float*)d_in[9];
    const float* fc2w  = (const float*)d_in[10];
    const float* fc2b  = (const float*)d_in[11];
    float* out = (float*)d_out;

    float *diagg, *x1, *x2;
    unsigned *hh, *hl, *aoh, *h2h, *mlph;
    __half *wqkvh, *wqkvl, *wprojh, *wfc1h, *wfc2h, *attnh, *qh, *ql, *kh, *kl, *vh;
    cudaGetSymbolAddress((void**)&diagg, g_diag);
    cudaGetSymbolAddress((void**)&attnh, g_attnh);
    cudaGetSymbolAddress((void**)&x1,   g_x1);
    cudaGetSymbolAddress((void**)&x2,   g_x2);
    cudaGetSymbolAddress((void**)&hh,   g_hh);
    cudaGetSymbolAddress((void**)&hl,   g_hl);
    cudaGetSymbolAddress((void**)&wqkvh, g_wqkvh);
    cudaGetSymbolAddress((void**)&wqkvl, g_wqkvl);
    cudaGetSymbolAddress((void**)&wprojh, g_wprojh);
    cudaGetSymbolAddress((void**)&wfc1h, g_wfc1h);
    cudaGetSymbolAddress((void**)&wfc2h, g_wfc2h);
    cudaGetSymbolAddress((void**)&qh,   g_qh);
    cudaGetSymbolAddress((void**)&ql,   g_ql);
    cudaGetSymbolAddress((void**)&kh,   g_kh);
    cudaGetSymbolAddress((void**)&kl,   g_kl);
    cudaGetSymbolAddress((void**)&vh,   g_vh);
    cudaGetSymbolAddress((void**)&aoh,  g_aoh);
    cudaGetSymbolAddress((void**)&h2h,  g_h2h);
    cudaGetSymbolAddress((void**)&mlph, g_mlph);

    const int PROP_SMEM = (K_ * R_ + R_ * 64) * 4;
    cudaFuncSetAttribute(propagate_kernel, cudaFuncAttributeMaxDynamicSharedMemorySize, PROP_SMEM);
    const int SMEM_S256  = (ABUF + 32 * 264) * 4 * 2;   // split: 2 stages x (hi+lo)
    const int SMEM_CP256 = (ABUF + 32 * 264) * 3 * 2;   // cp.async: 3 stages
    const int SMEM_CP128 = (ABUF + 32 * 136) * 3 * 2;
    const int SMEM_FSMAV = (64*36*4 + 64*(PSTR/2)) * 4 + 128 * 4;
    cudaFuncSetAttribute(hgemm_kernel<1, 2, 256>, cudaFuncAttributeMaxDynamicSharedMemorySize, SMEM_S256);
    cudaFuncSetAttribute(hgemm_kernel<0, 3, 256>, cudaFuncAttributeMaxDynamicSharedMemorySize, SMEM_CP256);
    cudaFuncSetAttribute(hgemm_kernel<0, 0, 256>, cudaFuncAttributeMaxDynamicSharedMemorySize, SMEM_CP256);
    cudaFuncSetAttribute(hgemm_kernel<0, 1, 256>, cudaFuncAttributeMaxDynamicSharedMemorySize, SMEM_CP256);
    cudaFuncSetAttribute(hgemm_kernel<0, 0, 128>, cudaFuncAttributeMaxDynamicSharedMemorySize, SMEM_CP128);
    cudaFuncSetAttribute(fsmav_kernel, cudaFuncAttributeMaxDynamicSharedMemorySize, SMEM_FSMAV);

    // 0. weight conversion
    cvtw_all<<<(S3_ + 255) / 256, 256>>>(qkvw, projw, fc1w, fc2w,
                                         wqkvh, wqkvl, wprojh, wfc1h, wfc2h);
    // 1. LN1
    ln_pack_kernel<1><<<B_ * N_, 256>>>(x, n1g, n1b, hh, hl);
    // 2a. QK (split, register-staged)
    hgemm_kernel<1, 2, 256><<<dim3(6, 197), 256, SMEM_S256>>>(
        hh, hl, wqkvh, wqkvl, nullptr, nullptr, nullptr, nullptr,
        (unsigned*)qh, (unsigned*)ql, (unsigned*)kh, (unsigned*)kl, nullptr, 2304, C_, 0, 0);
    // 2b. V (cp.async)
    hgemm_kernel<0, 3, 256><<<dim3(3, 197), 256, SMEM_CP256>>>(
        hh, nullptr, wqkvh, nullptr, nullptr, nullptr, nullptr, nullptr,
        nullptr, nullptr, nullptr, nullptr, (unsigned*)vh, 2304, C_, 0, 1536);
    // 3. fused scores + softmax + AV
    fsmav_kernel<<<dim3(BH_, 4), 256, SMEM_FSMAV>>>(qh, ql, kh, kl, vh, diagg, attnh, aoh);
    // 4. proj + bias + residual (cp.async)
    hgemm_kernel<0, 0, 256><<<dim3(3, 197), 256, SMEM_CP256>>>(
        aoh, nullptr, wprojh, nullptr, projb, x, x1, nullptr,
        nullptr, nullptr, nullptr, nullptr, nullptr, C_, C_, C_, 0);
    // 5. propagation (selection fused in)
    propagate_kernel<<<BH_, 256, PROP_SMEM>>>(diagg, attnh, x1, x2);
    // 6. LN2
    ln_pack_kernel<0><<<B_ * K_, 256>>>(x2, n2g, n2b, h2h, nullptr);
    // 7. fc1 + gelu (cp.async)
    hgemm_kernel<0, 1, 256><<<dim3(12, 99), 256, SMEM_CP256>>>(
        h2h, nullptr, wfc1h, nullptr, fc1b, nullptr, nullptr, mlph,
        nullptr, nullptr, nullptr, nullptr, nullptr, 4 * C_, C_, 0, 0);
    // 8. fc2 + residual -> out (cp.async, NT=128)
    hgemm_kernel<0, 0, 128><<<dim3(6, 99), 256, SMEM_CP128>>>(
        mlph, nullptr, wfc2h, nullptr, fc2b, x2, out, nullptr,
        nullptr, nullptr, nullptr, nullptr, nullptr, C_, 4 * C_, C_, 0);
}